// round 11
// baseline (speedup 1.0000x reference)
#include <cuda_runtime.h>
#include <cuda_bf16.h>
#include <math.h>
#include <stdint.h>

// Problem constants
#define H   512
#define CE  128
#define WE  256
#define U_  2048
#define TC  16
#define B_  256
#define TW  64
#define WD  (2*H + WE)   // 1280 word-input dim

// ---------------- scratch (device globals; allocation-free) ----------------
__device__ float g_Xg_c[(size_t)U_ * TC * 2 * H];
__device__ float g_Xc_c[(size_t)U_ * TC * H];
__device__ float g_Hc [(size_t)2 * U_ * H];
__device__ float g_Uc [(size_t)2 * U_ * H];
__device__ float g_Xg_w[(size_t)B_ * TW * 2 * H];
__device__ float g_Xc_w[(size_t)B_ * TW * H];
__device__ float g_Hw [(size_t)2 * B_ * H];
__device__ float g_Uw [(size_t)2 * B_ * H];
__device__ float g_Pg [(size_t)U_ * 2 * H];     // unique-word x-proj (gates)
__device__ float g_Pc [(size_t)U_ * H];         // unique-word x-proj (cand)
__device__ float g_states[(size_t)B_ * 2 * H];
__device__ float g_hidden[(size_t)B_ * 64];
// per-(step,phase,mtile) group-barrier counters: char 2*16*32, word 2*64*8
__device__ int   g_bar[2 * TC * 32 + 2 * TW * 8];
// length-sort permutations (rows sorted by len descending)
__device__ int g_perm_c[U_], g_iperm_c[U_];
__device__ int g_perm_w[B_], g_iperm_w[B_];

// split-bf16 A-operand images (tiled 128x32)
__device__ __align__(16) __nv_bfloat16 g_cAh[(size_t)U_ * TC * CE];
__device__ __align__(16) __nv_bfloat16 g_cAl[(size_t)U_ * TC * CE];
__device__ __align__(16) __nv_bfloat16 g_uAh[(size_t)U_ * 2 * H];
__device__ __align__(16) __nv_bfloat16 g_uAl[(size_t)U_ * 2 * H];
__device__ __align__(16) __nv_bfloat16 g_weAh[(size_t)B_ * TW * WE];
__device__ __align__(16) __nv_bfloat16 g_weAl[(size_t)B_ * TW * WE];
__device__ __align__(16) __nv_bfloat16 g_Hch[(size_t)2 * U_ * H];
__device__ __align__(16) __nv_bfloat16 g_Hcl[(size_t)2 * U_ * H];
__device__ __align__(16) __nv_bfloat16 g_RHh[(size_t)2 * U_ * H];
__device__ __align__(16) __nv_bfloat16 g_RHl[(size_t)2 * U_ * H];
__device__ __align__(16) __nv_bfloat16 g_Hwh[(size_t)2 * B_ * H];
__device__ __align__(16) __nv_bfloat16 g_Hwl[(size_t)2 * B_ * H];
__device__ __align__(16) __nv_bfloat16 g_RHwh[(size_t)2 * B_ * H];
__device__ __align__(16) __nv_bfloat16 g_RHwl[(size_t)2 * B_ * H];
// split-bf16 weights ([N,K] k-major tiled 128x32)
__device__ __align__(16) __nv_bfloat16 g_Wgc_h[(size_t)CE * 1024], g_Wgc_l[(size_t)CE * 1024];
__device__ __align__(16) __nv_bfloat16 g_Wcc_h[(size_t)CE * 512],  g_Wcc_l[(size_t)CE * 512];
__device__ __align__(16) __nv_bfloat16 g_Wgwcs_h[(size_t)1024 * 1024], g_Wgwcs_l[(size_t)1024 * 1024];
__device__ __align__(16) __nv_bfloat16 g_Wcwcs_h[(size_t)1024 * 512],  g_Wcwcs_l[(size_t)1024 * 512];
__device__ __align__(16) __nv_bfloat16 g_Wgwwe_h[(size_t)WE * 1024], g_Wgwwe_l[(size_t)WE * 1024];
__device__ __align__(16) __nv_bfloat16 g_Wcwwe_h[(size_t)WE * 512],  g_Wcwwe_l[(size_t)WE * 512];
__device__ __align__(16) __nv_bfloat16 g_Wghc_h[(size_t)H * 1024], g_Wghc_l[(size_t)H * 1024];
__device__ __align__(16) __nv_bfloat16 g_Wchc_h[(size_t)H * 512],  g_Wchc_l[(size_t)H * 512];
__device__ __align__(16) __nv_bfloat16 g_Wghw_h[(size_t)H * 1024], g_Wghw_l[(size_t)H * 1024];
__device__ __align__(16) __nv_bfloat16 g_Wchw_h[(size_t)H * 512],  g_Wchw_l[(size_t)H * 512];

// ---------------- helpers ----------------------------------------------------
__device__ __forceinline__ uint32_t smem_u32(const void* p) {
    uint32_t a;
    asm("{ .reg .u64 t; cvta.to.shared.u64 t, %1; cvt.u32.u64 %0, t; }" : "=r"(a) : "l"(p));
    return a;
}
__device__ __forceinline__ void split2(float v, __nv_bfloat16& h, __nv_bfloat16& l) {
    h = __float2bfloat16(v);
    l = __float2bfloat16(v - __bfloat162float(h));
}
__device__ __forceinline__ unsigned pack_bf(__nv_bfloat16 a, __nv_bfloat16 b) {
    unsigned short x = *(unsigned short*)&a, y = *(unsigned short*)&b;
    return (unsigned)x | ((unsigned)y << 16);
}
__device__ __forceinline__ size_t tiled_off(int row, int col, int NKt) {
    return ((size_t)((row >> 7) * NKt + (col >> 5)) * 128 + (row & 127)) * 32 + (col & 31);
}
__device__ __forceinline__ void ldm4(uint32_t r[4], uint32_t saddr) {
    asm volatile("ldmatrix.sync.aligned.m8n8.x4.shared.b16 {%0,%1,%2,%3}, [%4];"
                 : "=r"(r[0]), "=r"(r[1]), "=r"(r[2]), "=r"(r[3]) : "r"(saddr));
}
__device__ __forceinline__ void mma16816(float c[4], const uint32_t a[4], const uint32_t b[2]) {
    asm volatile(
        "mma.sync.aligned.m16n8k16.row.col.f32.bf16.bf16.f32 "
        "{%0,%1,%2,%3},{%4,%5,%6,%7},{%8,%9},{%0,%1,%2,%3};"
        : "+f"(c[0]), "+f"(c[1]), "+f"(c[2]), "+f"(c[3])
        : "r"(a[0]), "r"(a[1]), "r"(a[2]), "r"(a[3]), "r"(b[0]), "r"(b[1]));
}

// packed f32x2 (FFMA2) helpers for the scalar path
__device__ __forceinline__ unsigned long long pk2(float x) {
    unsigned long long d;
    unsigned u = __float_as_uint(x);
    asm("mov.b64 %0, {%1, %1};" : "=l"(d) : "r"(u));
    return d;
}
__device__ __forceinline__ void ffma2(unsigned long long& d,
                                      unsigned long long a,
                                      unsigned long long b) {
    asm("fma.rn.f32x2 %0, %1, %2, %0;" : "+l"(d) : "l"(a), "l"(b));
}
__device__ __forceinline__ float pick2(unsigned long long v, int half) {
    return __uint_as_float(half ? (unsigned)(v >> 32) : (unsigned)v);
}

// group barrier: n CTAs of one dependence group rendezvous on bar[idx]
__device__ __forceinline__ void grid_bar(int* bar, int idx, int n) {
    __syncthreads();
    if (threadIdx.x == 0) {
        __threadfence();
        atomicAdd(&bar[idx], 1);
        while (((volatile int*)bar)[idx] < n) __nanosleep(32);
        __threadfence();
    }
    __syncthreads();
}

// =============== split-bf16 mma.sync core: 128x128 tile, 256 thr ============
template<bool CG>
__device__ __forceinline__ void mma_core(
    const __nv_bfloat16* __restrict__ Ah, const __nv_bfloat16* __restrict__ Al,
    const __nv_bfloat16* __restrict__ Bh, const __nv_bfloat16* __restrict__ Bl,
    int NKt, int mt, int nt, float acc[4][4][4])
{
    __shared__ __align__(16) __nv_bfloat16 sA[2][128][40];
    __shared__ __align__(16) __nv_bfloat16 sB[2][128][40];
    const int tid = threadIdx.x, lane = tid & 31, warp = tid >> 5;
    const int wy = warp >> 2, wx = warp & 3;
    const int gq = lane >> 3, rr = lane & 7;
    uint4 pA[2][2], pB[2][2];

    auto gload = [&](int c) {
        #pragma unroll
        for (int i = 0; i < 2; i++) {
            int idx = tid + i * 256;
            int r = idx >> 2, c8 = idx & 3;
            size_t ta = ((size_t)(mt * NKt + c) * 128 + r) * 32 + c8 * 8;
            size_t tb = ((size_t)(nt * NKt + c) * 128 + r) * 32 + c8 * 8;
            if (CG) {
                pA[0][i] = __ldcg((const uint4*)(Ah + ta));
                pA[1][i] = __ldcg((const uint4*)(Al + ta));
            } else {
                pA[0][i] = *(const uint4*)(Ah + ta);
                pA[1][i] = *(const uint4*)(Al + ta);
            }
            pB[0][i] = *(const uint4*)(Bh + tb);
            pB[1][i] = *(const uint4*)(Bl + tb);
        }
    };
    auto sstore = [&]() {
        #pragma unroll
        for (int i = 0; i < 2; i++) {
            int idx = tid + i * 256;
            int r = idx >> 2, c8 = idx & 3;
            *(uint4*)&sA[0][r][c8 * 8] = pA[0][i];
            *(uint4*)&sA[1][r][c8 * 8] = pA[1][i];
            *(uint4*)&sB[0][r][c8 * 8] = pB[0][i];
            *(uint4*)&sB[1][r][c8 * 8] = pB[1][i];
        }
    };
    const uint32_t bAh = smem_u32(&sA[0][0][0]), bAl = smem_u32(&sA[1][0][0]);
    const uint32_t bBh = smem_u32(&sB[0][0][0]), bBl = smem_u32(&sB[1][0][0]);

    gload(0);
    for (int c = 0;;) {
        sstore();
        __syncthreads();
        int cn = c + 1;
        if (cn < NKt) gload(cn);
        #pragma unroll
        for (int s = 0; s < 2; s++) {
            uint32_t ah[4][4], al[4][4], bh[4][2], bl[4][2];
            #pragma unroll
            for (int mi = 0; mi < 4; mi++) {
                int row = wy * 64 + mi * 16 + (gq & 1) * 8 + rr;
                int col = s * 16 + (gq >> 1) * 8;
                uint32_t off = (uint32_t)(row * 40 + col) * 2;
                ldm4(ah[mi], bAh + off);
                ldm4(al[mi], bAl + off);
            }
            #pragma unroll
            for (int nb = 0; nb < 2; nb++) {
                int nrow = wx * 32 + nb * 16 + (gq >> 1) * 8 + rr;
                int col = s * 16 + (gq & 1) * 8;
                uint32_t off = (uint32_t)(nrow * 40 + col) * 2;
                uint32_t t0[4], t1[4];
                ldm4(t0, bBh + off);
                ldm4(t1, bBl + off);
                bh[nb * 2][0] = t0[0]; bh[nb * 2][1] = t0[1];
                bh[nb * 2 + 1][0] = t0[2]; bh[nb * 2 + 1][1] = t0[3];
                bl[nb * 2][0] = t1[0]; bl[nb * 2][1] = t1[1];
                bl[nb * 2 + 1][0] = t1[2]; bl[nb * 2 + 1][1] = t1[3];
            }
            #pragma unroll
            for (int mi = 0; mi < 4; mi++)
                #pragma unroll
                for (int ni = 0; ni < 4; ni++) {
                    mma16816(acc[mi][ni], ah[mi], bh[ni]);
                    mma16816(acc[mi][ni], ah[mi], bl[ni]);
                    mma16816(acc[mi][ni], al[mi], bh[ni]);
                }
        }
        __syncthreads();
        c = cn;
        if (c >= NKt) break;
    }
}

// =============== split-bf16 mma.sync core: 64x64 tile, 128 thr, CG A-loads ==
__device__ __forceinline__ void mma_core64cg(
    const __nv_bfloat16* __restrict__ Ah, const __nv_bfloat16* __restrict__ Al,
    const __nv_bfloat16* __restrict__ Bh, const __nv_bfloat16* __restrict__ Bl,
    int NKt, int bm, int bn, float acc[4][2][4])
{
    __shared__ __align__(16) __nv_bfloat16 sA[2][64][40];
    __shared__ __align__(16) __nv_bfloat16 sB[2][64][40];
    const int tid = threadIdx.x, lane = tid & 31, wx = tid >> 5;
    const int gq = lane >> 3, rr = lane & 7;
    uint4 pA[2][2], pB[2][2];
    const int mtb = bm >> 7, mro = bm & 127;
    const int ntb = bn >> 7, nro = bn & 127;

    auto gload = [&](int c) {
        #pragma unroll
        for (int i = 0; i < 2; i++) {
            int idx = tid + i * 128;
            int r = idx >> 2, c8 = idx & 3;
            size_t ta = ((size_t)(mtb * NKt + c) * 128 + mro + r) * 32 + c8 * 8;
            size_t tb = ((size_t)(ntb * NKt + c) * 128 + nro + r) * 32 + c8 * 8;
            pA[0][i] = __ldcg((const uint4*)(Ah + ta));
            pA[1][i] = __ldcg((const uint4*)(Al + ta));
            pB[0][i] = *(const uint4*)(Bh + tb);
            pB[1][i] = *(const uint4*)(Bl + tb);
        }
    };
    auto sstore = [&]() {
        #pragma unroll
        for (int i = 0; i < 2; i++) {
            int idx = tid + i * 128;
            int r = idx >> 2, c8 = idx & 3;
            *(uint4*)&sA[0][r][c8 * 8] = pA[0][i];
            *(uint4*)&sA[1][r][c8 * 8] = pA[1][i];
            *(uint4*)&sB[0][r][c8 * 8] = pB[0][i];
            *(uint4*)&sB[1][r][c8 * 8] = pB[1][i];
        }
    };
    const uint32_t bAh = smem_u32(&sA[0][0][0]), bAl = smem_u32(&sA[1][0][0]);
    const uint32_t bBh = smem_u32(&sB[0][0][0]), bBl = smem_u32(&sB[1][0][0]);

    gload(0);
    for (int c = 0;;) {
        sstore();
        __syncthreads();
        int cn = c + 1;
        if (cn < NKt) gload(cn);
        #pragma unroll
        for (int s = 0; s < 2; s++) {
            uint32_t ah[4][4], al[4][4], bh[2][2], bl[2][2];
            #pragma unroll
            for (int mi = 0; mi < 4; mi++) {
                int row = mi * 16 + (gq & 1) * 8 + rr;
                int col = s * 16 + (gq >> 1) * 8;
                uint32_t off = (uint32_t)(row * 40 + col) * 2;
                ldm4(ah[mi], bAh + off);
                ldm4(al[mi], bAl + off);
            }
            {
                int nrow = wx * 16 + (gq >> 1) * 8 + rr;
                int col = s * 16 + (gq & 1) * 8;
                uint32_t off = (uint32_t)(nrow * 40 + col) * 2;
                uint32_t t0[4], t1[4];
                ldm4(t0, bBh + off);
                ldm4(t1, bBl + off);
                bh[0][0] = t0[0]; bh[0][1] = t0[1];
                bh[1][0] = t0[2]; bh[1][1] = t0[3];
                bl[0][0] = t1[0]; bl[0][1] = t1[1];
                bl[1][0] = t1[2]; bl[1][1] = t1[3];
            }
            #pragma unroll
            for (int mi = 0; mi < 4; mi++)
                #pragma unroll
                for (int ni = 0; ni < 2; ni++) {
                    mma16816(acc[mi][ni], ah[mi], bh[ni]);
                    mma16816(acc[mi][ni], ah[mi], bl[ni]);
                    mma16816(acc[mi][ni], al[mi], bh[ni]);
                }
        }
        __syncthreads();
        c = cn;
        if (c >= NKt) break;
    }
}

// ---- GEMM + bias: C[M,Nd] fp32 = A@W + bias (ACC: C += A@W, no bias) ----
template<bool ACC>
__global__ void __launch_bounds__(256)
k_mm_bias_t(const __nv_bfloat16* __restrict__ Ah, const __nv_bfloat16* __restrict__ Al,
            const __nv_bfloat16* __restrict__ Bh, const __nv_bfloat16* __restrict__ Bl,
            const float* __restrict__ bias, float* __restrict__ C, int Nd, int NKt)
{
    float acc[4][4][4] = {};
    int nt = blockIdx.x, mt = blockIdx.y;
    mma_core<false>(Ah, Al, Bh, Bl, NKt, mt, nt, acc);
    int lane = threadIdx.x & 31, warp = threadIdx.x >> 5;
    int wy = warp >> 2, wx = warp & 3;
    int bm = mt * 128, bn = nt * 128;
    #pragma unroll
    for (int mi = 0; mi < 4; mi++) {
        #pragma unroll
        for (int ni = 0; ni < 4; ni++) {
            int n0 = bn + wx * 32 + ni * 8 + (lane & 3) * 2;
            int r0 = bm + wy * 64 + mi * 16 + (lane >> 2);
            float* p0 = C + (size_t)r0 * Nd + n0;
            float* p1 = C + (size_t)(r0 + 8) * Nd + n0;
            float2 v0, v1;
            if (ACC) {
                float2 o0 = *(float2*)p0, o1 = *(float2*)p1;
                v0 = {acc[mi][ni][0] + o0.x, acc[mi][ni][1] + o0.y};
                v1 = {acc[mi][ni][2] + o1.x, acc[mi][ni][3] + o1.y};
            } else {
                v0 = {acc[mi][ni][0] + bias[n0], acc[mi][ni][1] + bias[n0 + 1]};
                v1 = {acc[mi][ni][2] + bias[n0], acc[mi][ni][3] + bias[n0 + 1]};
            }
            *(float2*)p0 = v0;
            *(float2*)p1 = v1;
        }
    }
}

// ---- length argsort (descending, stable): perm[rank]=i, iperm[i]=rank ----
__global__ void k_sort(const int* __restrict__ lens, int n,
                       int* __restrict__ perm, int* __restrict__ iperm) {
    extern __shared__ int sl[];
    for (int j = threadIdx.x; j < n; j += blockDim.x) sl[j] = lens[j];
    __syncthreads();
    for (int i = blockIdx.x * blockDim.x + threadIdx.x; i < n; i += blockDim.x * gridDim.x) {
        int li = sl[i], rank = 0;
        for (int j = 0; j < n; j++) {
            int lj = sl[j];
            rank += (lj > li) || (lj == li && j < i);
        }
        perm[rank] = i;
        iperm[i] = rank;
    }
}

// ==================== PERSISTENT char bi-GRU (length-sorted rows) ===========
// Row r handles word form perm[r (mod U)]. Group mt exits at its max length.
__global__ void __launch_bounds__(256)
k_char_rnn(const __nv_bfloat16* __restrict__ Wgh_h, const __nv_bfloat16* __restrict__ Wgh_l,
           const __nv_bfloat16* __restrict__ Wch_h, const __nv_bfloat16* __restrict__ Wch_l,
           const float* __restrict__ Xg, const float* __restrict__ Xc,
           const int* __restrict__ lens, const int* __restrict__ perm,
           float* __restrict__ Hfp, float* __restrict__ Ug,
           __nv_bfloat16* __restrict__ Hh, __nv_bfloat16* __restrict__ Hl,
           __nv_bfloat16* __restrict__ RHh, __nv_bfloat16* __restrict__ RHl,
           int* __restrict__ bar)
{
    const int lane = threadIdx.x & 31, warp = threadIdx.x >> 5;
    const int wy = warp >> 2, wx = warp & 3;
    const int Nseq = U_, T = TC;
    const int mt = blockIdx.x >> 2;
    const int sub = blockIdx.x & 3;
    const int bm = mt * 128;
    // group max length (rows sorted descending by len): first row of group
    const int tmax = lens[perm[(bm >= Nseq) ? (bm - Nseq) : bm]];

    #pragma unroll 1
    for (int t = 0; t < tmax; t++) {
        // ---------- gates: 2 n-tiles per CTA, same mt ----------
        #pragma unroll 1
        for (int rep = 0; rep < 2; rep++) {
            int nt = sub * 2 + rep;
            float acc[4][4][4] = {};
            mma_core<true>(Hh, Hl, Wgh_h, Wgh_l, H / 32, mt, nt, acc);
            int bn = nt * 128;
            bool isR = (bn + 128 <= H);
            #pragma unroll
            for (int mi = 0; mi < 4; mi++) {
                #pragma unroll
                for (int hh = 0; hh < 2; hh++) {
                    int r = bm + wy * 64 + mi * 16 + (lane >> 2) + hh * 8;
                    int dir = (r >= Nseq);
                    int n = perm[dir ? r - Nseq : r];
                    int len = lens[n];
                    int te = dir ? max(0, min(len - 1 - t, T - 1)) : t;
                    const float* xg = Xg + ((size_t)n * T + te) * (2 * H);
                    #pragma unroll
                    for (int ni = 0; ni < 4; ni++) {
                        int c0 = bn + wx * 32 + ni * 8 + (lane & 3) * 2;
                        float a0 = acc[mi][ni][hh * 2 + 0];
                        float a1 = acc[mi][ni][hh * 2 + 1];
                        float g0 = 1.f / (1.f + __expf(-(xg[c0] + a0)));
                        float g1 = 1.f / (1.f + __expf(-(xg[c0 + 1] + a1)));
                        if (isR) {
                            float2 hv = __ldcg((const float2*)(Hfp + (size_t)r * H + c0));
                            float rh0 = g0 * hv.x, rh1 = g1 * hv.y;
                            __nv_bfloat16 h0, l0, h1, l1;
                            split2(rh0, h0, l0);
                            split2(rh1, h1, l1);
                            size_t o = tiled_off(r, c0, H / 32);
                            __stcg((unsigned*)(RHh + o), pack_bf(h0, h1));
                            __stcg((unsigned*)(RHl + o), pack_bf(l0, l1));
                        } else {
                            float2 uv = {g0, g1};
                            __stcg((float2*)(Ug + (size_t)r * H + (c0 - H)), uv);
                        }
                    }
                }
            }
        }
        grid_bar(bar, 2 * t * 32 + mt, 4);

        // ---------- cand: 1 n-tile per CTA, same mt ----------
        {
            int nt = sub;
            float acc[4][4][4] = {};
            mma_core<true>(RHh, RHl, Wch_h, Wch_l, H / 32, mt, nt, acc);
            int bn = nt * 128;
            #pragma unroll
            for (int mi = 0; mi < 4; mi++) {
                #pragma unroll
                for (int hh = 0; hh < 2; hh++) {
                    int r = bm + wy * 64 + mi * 16 + (lane >> 2) + hh * 8;
                    int dir = (r >= Nseq);
                    int n = perm[dir ? r - Nseq : r];
                    int len = lens[n];
                    if (t >= len) continue;   // frozen
                    int te = dir ? max(0, min(len - 1 - t, T - 1)) : t;
                    const float* xc = Xc + ((size_t)n * T + te) * H;
                    #pragma unroll
                    for (int ni = 0; ni < 4; ni++) {
                        int c0 = bn + wx * 32 + ni * 8 + (lane & 3) * 2;
                        float cc0 = tanhf(xc[c0] + acc[mi][ni][hh * 2 + 0]);
                        float cc1 = tanhf(xc[c0 + 1] + acc[mi][ni][hh * 2 + 1]);
                        float2 hv = __ldcg((const float2*)(Hfp + (size_t)r * H + c0));
                        float2 uv = __ldcg((const float2*)(Ug + (size_t)r * H + c0));
                        float hn0 = uv.x * hv.x + (1.f - uv.x) * cc0;
                        float hn1 = uv.y * hv.y + (1.f - uv.y) * cc1;
                        float2 hw = {hn0, hn1};
                        __stcg((float2*)(Hfp + (size_t)r * H + c0), hw);
                        __nv_bfloat16 h0, l0, h1, l1;
                        split2(hn0, h0, l0);
                        split2(hn1, h1, l1);
                        size_t o = tiled_off(r, c0, H / 32);
                        __stcg((unsigned*)(Hh + o), pack_bf(h0, h1));
                        __stcg((unsigned*)(Hl + o), pack_bf(l0, l1));
                    }
                }
            }
        }
        grid_bar(bar, (2 * t + 1) * 32 + mt, 4);
    }
}

// ==================== PERSISTENT word bi-GRU (length-sorted rows) ===========
__global__ void __launch_bounds__(128)
k_word_rnn(const __nv_bfloat16* __restrict__ Wgh_h, const __nv_bfloat16* __restrict__ Wgh_l,
           const __nv_bfloat16* __restrict__ Wch_h, const __nv_bfloat16* __restrict__ Wch_l,
           const float* __restrict__ Xg, const float* __restrict__ Xc,
           const int* __restrict__ lens, const int* __restrict__ perm,
           float* __restrict__ Hfp, float* __restrict__ Ug,
           __nv_bfloat16* __restrict__ Hh, __nv_bfloat16* __restrict__ Hl,
           __nv_bfloat16* __restrict__ RHh, __nv_bfloat16* __restrict__ RHl,
           int* __restrict__ bar)
{
    const int cta = blockIdx.x;
    const int mtile = cta >> 4, ntile = cta & 15;
    const int bm = mtile * 64;
    const int lane = threadIdx.x & 31, wx = threadIdx.x >> 5;
    const int Nseq = B_, T = TW;
    const int tmax = lens[perm[(bm >= Nseq) ? (bm - Nseq) : bm]];

    #pragma unroll 1
    for (int t = 0; t < tmax; t++) {
        // ---------- gates ----------
        {
            float acc[4][2][4] = {};
            int bn = ntile * 64;
            mma_core64cg(Hh, Hl, Wgh_h, Wgh_l, H / 32, bm, bn, acc);
            bool isR = (bn + 64 <= H);
            #pragma unroll
            for (int mi = 0; mi < 4; mi++) {
                #pragma unroll
                for (int hh = 0; hh < 2; hh++) {
                    int r = bm + mi * 16 + (lane >> 2) + hh * 8;
                    int dir = (r >= Nseq);
                    int n = perm[dir ? r - Nseq : r];
                    int len = lens[n];
                    int te = dir ? max(0, min(len - 1 - t, T - 1)) : t;
                    const float* xg = Xg + ((size_t)n * T + te) * (2 * H);
                    #pragma unroll
                    for (int ni = 0; ni < 2; ni++) {
                        int c0 = bn + wx * 16 + ni * 8 + (lane & 3) * 2;
                        float a0 = acc[mi][ni][hh * 2 + 0];
                        float a1 = acc[mi][ni][hh * 2 + 1];
                        float g0 = 1.f / (1.f + __expf(-(xg[c0] + a0)));
                        float g1 = 1.f / (1.f + __expf(-(xg[c0 + 1] + a1)));
                        if (isR) {
                            float2 hv = __ldcg((const float2*)(Hfp + (size_t)r * H + c0));
                            float rh0 = g0 * hv.x, rh1 = g1 * hv.y;
                            __nv_bfloat16 h0, l0, h1, l1;
                            split2(rh0, h0, l0);
                            split2(rh1, h1, l1);
                            size_t o = tiled_off(r, c0, H / 32);
                            __stcg((unsigned*)(RHh + o), pack_bf(h0, h1));
                            __stcg((unsigned*)(RHl + o), pack_bf(l0, l1));
                        } else {
                            float2 uv = {g0, g1};
                            __stcg((float2*)(Ug + (size_t)r * H + (c0 - H)), uv);
                        }
                    }
                }
            }
        }
        grid_bar(bar, 2 * t * 8 + mtile, 16);

        // ---------- cand ----------
        if (ntile < 8) {
            float acc[4][2][4] = {};
            int bn = ntile * 64;
            mma_core64cg(RHh, RHl, Wch_h, Wch_l, H / 32, bm, bn, acc);
            #pragma unroll
            for (int mi = 0; mi < 4; mi++) {
                #pragma unroll
                for (int hh = 0; hh < 2; hh++) {
                    int r = bm + mi * 16 + (lane >> 2) + hh * 8;
                    int dir = (r >= Nseq);
                    int n = perm[dir ? r - Nseq : r];
                    int len = lens[n];
                    if (t >= len) continue;   // frozen
                    int te = dir ? max(0, min(len - 1 - t, T - 1)) : t;
                    const float* xc = Xc + ((size_t)n * T + te) * H;
                    #pragma unroll
                    for (int ni = 0; ni < 2; ni++) {
                        int c0 = bn + wx * 16 + ni * 8 + (lane & 3) * 2;
                        float cc0 = tanhf(xc[c0] + acc[mi][ni][hh * 2 + 0]);
                        float cc1 = tanhf(xc[c0 + 1] + acc[mi][ni][hh * 2 + 1]);
                        float2 hv = __ldcg((const float2*)(Hfp + (size_t)r * H + c0));
                        float2 uv = __ldcg((const float2*)(Ug + (size_t)r * H + c0));
                        float hn0 = uv.x * hv.x + (1.f - uv.x) * cc0;
                        float hn1 = uv.y * hv.y + (1.f - uv.y) * cc1;
                        float2 hw = {hn0, hn1};
                        __stcg((float2*)(Hfp + (size_t)r * H + c0), hw);
                        __nv_bfloat16 h0, l0, h1, l1;
                        split2(hn0, h0, l0);
                        split2(hn1, h1, l1);
                        size_t o = tiled_off(r, c0, H / 32);
                        __stcg((unsigned*)(Hh + o), pack_bf(h0, h1));
                        __stcg((unsigned*)(Hl + o), pack_bf(l0, l1));
                    }
                }
            }
        }
        grid_bar(bar, (2 * t + 1) * 8 + mtile, 16);
    }
}

// ---- fused one-time weight split (all 10 segments in one launch) ----
__device__ __forceinline__ void prep1(const float* W, int idx, int Nd, int NKt,
                                      __nv_bfloat16* Bh, __nv_bfloat16* Bl) {
    int k = idx / Nd, n = idx % Nd;
    __nv_bfloat16 h, l;
    split2(W[idx], h, l);
    size_t off = ((size_t)((n >> 7) * NKt + (k >> 5)) * 128 + (n & 127)) * 32 + (k & 31);
    Bh[off] = h; Bl[off] = l;
}

#define Q1 (CE * 1024)
#define Q2 (Q1 + CE * 512)
#define Q3 (Q2 + 1024 * 1024)
#define Q4 (Q3 + 1024 * 512)
#define Q5 (Q4 + WE * 1024)
#define Q6 (Q5 + WE * 512)
#define Q7 (Q6 + H * 1024)
#define Q8 (Q7 + H * 512)
#define Q9 (Q8 + H * 1024)
#define Q10 (Q9 + H * 512)

__global__ void k_prep_all(const float* __restrict__ Wg_c, const float* __restrict__ Wc_c,
                           const float* __restrict__ Wg_w, const float* __restrict__ Wc_w,
                           __nv_bfloat16* Wgc_h, __nv_bfloat16* Wgc_l,
                           __nv_bfloat16* Wcc_h, __nv_bfloat16* Wcc_l,
                           __nv_bfloat16* Wgwcs_h, __nv_bfloat16* Wgwcs_l,
                           __nv_bfloat16* Wcwcs_h, __nv_bfloat16* Wcwcs_l,
                           __nv_bfloat16* Wgwwe_h, __nv_bfloat16* Wgwwe_l,
                           __nv_bfloat16* Wcwwe_h, __nv_bfloat16* Wcwwe_l,
                           __nv_bfloat16* Wghc_h, __nv_bfloat16* Wghc_l,
                           __nv_bfloat16* Wchc_h, __nv_bfloat16* Wchc_l,
                           __nv_bfloat16* Wghw_h, __nv_bfloat16* Wghw_l,
                           __nv_bfloat16* Wchw_h, __nv_bfloat16* Wchw_l) {
    int i = blockIdx.x * blockDim.x + threadIdx.x;
    if (i < Q1)      prep1(Wg_c, i, 1024, CE / 32, Wgc_h, Wgc_l);
    else if (i < Q2) prep1(Wc_c, i - Q1, 512, CE / 32, Wcc_h, Wcc_l);
    else if (i < Q3) prep1(Wg_w, i - Q2, 1024, 1024 / 32, Wgwcs_h, Wgwcs_l);
    else if (i < Q4) prep1(Wc_w, i - Q3, 512, 1024 / 32, Wcwcs_h, Wcwcs_l);
    else if (i < Q5) prep1(Wg_w + (size_t)1024 * 1024, i - Q4, 1024, WE / 32, Wgwwe_h, Wgwwe_l);
    else if (i < Q6) prep1(Wc_w + (size_t)1024 * 512, i - Q5, 512, WE / 32, Wcwwe_h, Wcwwe_l);
    else if (i < Q7) prep1(Wg_c + (size_t)CE * 1024, i - Q6, 1024, H / 32, Wghc_h, Wghc_l);
    else if (i < Q8) prep1(Wc_c + (size_t)CE * 512, i - Q7, 512, H / 32, Wchc_h, Wchc_l);
    else if (i < Q9) prep1(Wg_w + (size_t)WD * 1024, i - Q8, 1024, H / 32, Wghw_h, Wghw_l);
    else if (i < Q10) prep1(Wc_w + (size_t)WD * 512, i - Q9, 512, H / 32, Wchw_h, Wchw_l);
}

// ---- gathers / assembly kernels ---------------------------------------------
__global__ void k_gather_char_sp(const int* __restrict__ charseqs,
                                 const float* __restrict__ char_emb,
                                 __nv_bfloat16* __restrict__ Ah,
                                 __nv_bfloat16* __restrict__ Al, int total) {
    int i = blockIdx.x * blockDim.x + threadIdx.x;
    if (i >= total) return;
    int c = i & (CE - 1);
    int rowg = i >> 7;
    float v = char_emb[(size_t)charseqs[rowg] * CE + c];
    __nv_bfloat16 h, l;
    split2(v, h, l);
    size_t off = tiled_off(rowg, c, CE / 32);
    Ah[off] = h; Al[off] = l;
}

// build unique-word concat-state split image [U x 2H] from permuted Hc rows
__global__ void k_build_u(const float* __restrict__ Hc, const int* __restrict__ iperm,
                          __nv_bfloat16* __restrict__ Ah,
                          __nv_bfloat16* __restrict__ Al) {
    int i = blockIdx.x * blockDim.x + threadIdx.x;
    if (i >= U_ * 2 * H) return;
    int c = i & (2 * H - 1);
    int u = i >> 10;
    int rw = iperm[u];
    float v = (c < H) ? Hc[(size_t)rw * H + c] : Hc[(size_t)(U_ + rw) * H + (c - H)];
    __nv_bfloat16 h, l;
    split2(v, h, l);
    size_t off = tiled_off(u, c, (2 * H) / 32);
    Ah[off] = h; Al[off] = l;
}

// gather word embeddings only (WE cols) into split image [B*TW x WE]
__global__ void k_gather_we(const int* __restrict__ wids,
                            const float* __restrict__ word_emb,
                            __nv_bfloat16* __restrict__ Ah,
                            __nv_bfloat16* __restrict__ Al) {
    int i = blockIdx.x * blockDim.x + threadIdx.x;
    if (i >= B_ * TW * WE) return;
    int c = i & (WE - 1);
    int bt = i >> 8;
    float v = word_emb[(size_t)wids[bt] * WE + c];
    __nv_bfloat16 h, l;
    split2(v, h, l);
    size_t off = tiled_off(bt, c, WE / 32);
    Ah[off] = h; Al[off] = l;
}

// scatter unique projections to per-token X buffers (bias already in P)
__global__ void k_combine(const int* __restrict__ cids,
                          const float* __restrict__ Pg, const float* __restrict__ Pc,
                          float* __restrict__ Xg, float* __restrict__ Xc) {
    int i = blockIdx.x * blockDim.x + threadIdx.x;
    const int total = B_ * TW * 384;
    if (i >= total) return;
    int bt = i / 384, j = i % 384;
    int u = cids[bt];
    if (j < 256)
        ((float4*)Xg)[(size_t)bt * 256 + j] = ((const float4*)Pg)[(size_t)u * 256 + j];
    else
        ((float4*)Xc)[(size_t)bt * 128 + (j - 256)] = ((const float4*)Pc)[(size_t)u * 128 + (j - 256)];
}

// ============ small 64x64 / 4x4 FFMA2 core (head) ===========================
__device__ __forceinline__ void gemm64_2(const float* __restrict__ A,
                                         const float* __restrict__ Bm,
                                         int K, int N, int bm, int bn,
                                         unsigned long long acc[4][2]) {
    __shared__ float As[2][16][64];
    __shared__ float Bs[2][16][64];
    const int tid = threadIdx.x;
    const int tx = tid & 15;
    const int ty = tid >> 4;
    float4 aR, bR;
    auto loadA = [&](int k0) {
        int r = tid >> 2, c4 = tid & 3;
        aR = *(const float4*)(A + (size_t)(bm + r) * K + k0 + c4 * 4);
    };
    auto loadB = [&](int k0) {
        int kr = tid >> 4, c4 = tid & 15;
        bR = *(const float4*)(Bm + (size_t)(k0 + kr) * N + bn + c4 * 4);
    };
    auto stage = [&](int buf) {
        int r = tid >> 2, c4 = tid & 3;
        As[buf][c4 * 4 + 0][r] = aR.x;
        As[buf][c4 * 4 + 1][r] = aR.y;
        As[buf][c4 * 4 + 2][r] = aR.z;
        As[buf][c4 * 4 + 3][r] = aR.w;
        int kr = tid >> 4, cb = tid & 15;
        *(float4*)&Bs[buf][kr][cb * 4] = bR;
    };
    loadA(0); loadB(0);
    stage(0);
    __syncthreads();
    int buf = 0;
    for (int k0 = 0;;) {
        int kn = k0 + 16;
        if (kn < K) { loadA(kn); loadB(kn); }
        #pragma unroll
        for (int k = 0; k < 16; k++) {
            float4 a = *(const float4*)&As[buf][k][ty * 4];
            ulonglong2 bp = *(const ulonglong2*)&Bs[buf][k][tx * 4];
            float av[4] = {a.x, a.y, a.z, a.w};
            #pragma unroll
            for (int i = 0; i < 4; i++) {
                unsigned long long ad = pk2(av[i]);
                ffma2(acc[i][0], ad, bp.x);
                ffma2(acc[i][1], ad, bp.y);
            }
        }
        if (kn >= K) break;
        stage(buf ^ 1);
        __syncthreads();
        buf ^= 1;
        k0 = kn;
    }
}

__global__ __launch_bounds__(256)
void k_sgemm_bias_s(const float* __restrict__ A, const float* __restrict__ Bm,
                    const float* __restrict__ bias, float* __restrict__ C,
                    int N, int K, int act) {
    unsigned long long acc[4][2] = {};
    int bm = blockIdx.y * 64, bn = blockIdx.x * 64;
    gemm64_2(A, Bm, K, N, bm, bn, acc);
    const int tx = threadIdx.x & 15, ty = threadIdx.x >> 4;
    #pragma unroll
    for (int i = 0; i < 4; i++) {
        int r = bm + ty * 4 + i;
        #pragma unroll
        for (int q = 0; q < 4; q++) {
            int c = bn + tx * 4 + q;
            float v = pick2(acc[i][q >> 1], q & 1) + bias[c];
            if (act) v = v > 0.f ? v : 0.2f * v;
            C[(size_t)r * N + c] = v;
        }
    }
}

// ---------------- misc small kernels -----------------------------------------
__global__ void k_copy_states(const float* __restrict__ Hw, const int* __restrict__ iperm,
                              float* __restrict__ out) {
    int i = blockIdx.x * blockDim.x + threadIdx.x;
    if (i >= B_ * 2 * H) return;
    int c = i % (2 * H);
    int b = i / (2 * H);
    int rw = iperm[b];
    out[i] = (c < H) ? Hw[(size_t)rw * H + c] : Hw[(size_t)(B_ + rw) * H + (c - H)];
}

__global__ void k_fc2(const float* __restrict__ hidden, const float* __restrict__ W2,
                      const float* __restrict__ b2, float* __restrict__ out) {
    int i = blockIdx.x * blockDim.x + threadIdx.x;
    if (i >= B_ * 2) return;
    int b = i >> 1, j = i & 1;
    float s = b2[j];
    #pragma unroll
    for (int k = 0; k < 64; k++) s = fmaf(hidden[b * 64 + k], W2[k * 2 + j], s);
    out[i] = s;
}

// ---------------- host orchestration ----------------------------------------
extern "C" void kernel_launch(void* const* d_in, const int* in_sizes, int n_in,
                              void* d_out, int out_size) {
    const int*   charseqs      = (const int*)d_in[0];
    const int*   charseq_lens  = (const int*)d_in[1];
    const int*   charseq_ids   = (const int*)d_in[2];
    const int*   word_ids      = (const int*)d_in[3];
    const int*   sentence_lens = (const int*)d_in[4];
    const float* char_emb      = (const float*)d_in[5];
    const float* word_emb      = (const float*)d_in[6];
    const float* Wg_c = (const float*)d_in[7];
    const float* bg_c = (const float*)d_in[8];
    const float* Wc_c = (const float*)d_in[9];
    const float* bc_c = (const float*)d_in[10];
    const float* Wg_w = (const float*)d_in[11];
    const float* bg_w = (const float*)d_in[12];
    const float* Wc_w = (const float*)d_in[13];
    const float* bc_w = (const float*)d_in[14];
    const float* W1   = (const float*)d_in[15];
    const float* b1   = (const float*)d_in[16];
    const float* W2   = (const float*)d_in[17];
    const float* b2   = (const float*)d_in[18];
    float* out = (float*)d_out;

    float *Xg_c, *Xc_c, *Hc, *Uc, *Xg_w, *Xc_w, *Hw, *Uw, *Pg, *Pc, *states, *hidden;
    int *bar, *perm_c, *iperm_c, *perm_w, *iperm_w;
    __nv_bfloat16 *cAh, *cAl, *uAh, *uAl, *weAh, *weAl, *Hch, *Hcl, *RHh, *RHl;
    __nv_bfloat16 *Hwh, *Hwl, *RHwh, *RHwl;
    __nv_bfloat16 *Wgc_h, *Wgc_l, *Wcc_h, *Wcc_l;
    __nv_bfloat16 *Wgwcs_h, *Wgwcs_l, *Wcwcs_h, *Wcwcs_l;
    __nv_bfloat16 *Wgwwe_h, *Wgwwe_l, *Wcwwe_h, *Wcwwe_l;
    __nv_bfloat16 *Wghc_h, *Wghc_l, *Wchc_h, *Wchc_l, *Wghw_h, *Wghw_l, *Wchw_h, *Wchw_l;
    cudaGetSymbolAddress((void**)&Xg_c,   g_Xg_c);
    cudaGetSymbolAddress((void**)&Xc_c,   g_Xc_c);
    cudaGetSymbolAddress((void**)&Hc,     g_Hc);
    cudaGetSymbolAddress((void**)&Uc,     g_Uc);
    cudaGetSymbolAddress((void**)&Xg_w,   g_Xg_w);
    cudaGetSymbolAddress((void**)&Xc_w,   g_Xc_w);
    cudaGetSymbolAddress((void**)&Hw,     g_Hw);
    cudaGetSymbolAddress((void**)&Uw,     g_Uw);
    cudaGetSymbolAddress((void**)&Pg,     g_Pg);
    cudaGetSymbolAddress((void**)&Pc,     g_Pc);
    cudaGetSymbolAddress((void**)&states, g_states);
    cudaGetSymbolAddress((void**)&hidden, g_hidden);
    cudaGetSymbolAddress((void**)&bar,    g_bar);
    cudaGetSymbolAddress((void**)&perm_c, g_perm_c);
    cudaGetSymbolAddress((void**)&iperm_c, g_iperm_c);
    cudaGetSymbolAddress((void**)&perm_w, g_perm_w);
    cudaGetSymbolAddress((void**)&iperm_w, g_iperm_w);
    cudaGetSymbolAddress((void**)&cAh, g_cAh);
    cudaGetSymbolAddress((void**)&cAl, g_cAl);
    cudaGetSymbolAddress((void**)&uAh, g_uAh);
    cudaGetSymbolAddress((void**)&uAl, g_uAl);
    cudaGetSymbolAddress((void**)&weAh, g_weAh);
    cudaGetSymbolAddress((void**)&weAl, g_weAl);
    cudaGetSymbolAddress((void**)&Hch, g_Hch);
    cudaGetSymbolAddress((void**)&Hcl, g_Hcl);
    cudaGetSymbolAddress((void**)&RHh, g_RHh);
    cudaGetSymbolAddress((void**)&RHl, g_RHl);
    cudaGetSymbolAddress((void**)&Hwh, g_Hwh);
    cudaGetSymbolAddress((void**)&Hwl, g_Hwl);
    cudaGetSymbolAddress((void**)&RHwh, g_RHwh);
    cudaGetSymbolAddress((void**)&RHwl, g_RHwl);
    cudaGetSymbolAddress((void**)&Wgc_h, g_Wgc_h);
    cudaGetSymbolAddress((void**)&Wgc_l, g_Wgc_l);
    cudaGetSymbolAddress((void**)&Wcc_h, g_Wcc_h);
    cudaGetSymbolAddress((void**)&Wcc_l, g_Wcc_l);
    cudaGetSymbolAddress((void**)&Wgwcs_h, g_Wgwcs_h);
    cudaGetSymbolAddress((void**)&Wgwcs_l, g_Wgwcs_l);
    cudaGetSymbolAddress((void**)&Wcwcs_h, g_Wcwcs_h);
    cudaGetSymbolAddress((void**)&Wcwcs_l, g_Wcwcs_l);
    cudaGetSymbolAddress((void**)&Wgwwe_h, g_Wgwwe_h);
    cudaGetSymbolAddress((void**)&Wgwwe_l, g_Wgwwe_l);
    cudaGetSymbolAddress((void**)&Wcwwe_h, g_Wcwwe_h);
    cudaGetSymbolAddress((void**)&Wcwwe_l, g_Wcwwe_l);
    cudaGetSymbolAddress((void**)&Wghc_h, g_Wghc_h);
    cudaGetSymbolAddress((void**)&Wghc_l, g_Wghc_l);
    cudaGetSymbolAddress((void**)&Wchc_h, g_Wchc_h);
    cudaGetSymbolAddress((void**)&Wchc_l, g_Wchc_l);
    cudaGetSymbolAddress((void**)&Wghw_h, g_Wghw_h);
    cudaGetSymbolAddress((void**)&Wghw_l, g_Wghw_l);
    cudaGetSymbolAddress((void**)&Wchw_h, g_Wchw_h);
    cudaGetSymbolAddress((void**)&Wchw_l, g_Wchw_l);

    // ---- one fused weight-split launch + sorts ----
    k_prep_all<<<(Q10 + 255) / 256, 256>>>(Wg_c, Wc_c, Wg_w, Wc_w,
        Wgc_h, Wgc_l, Wcc_h, Wcc_l,
        Wgwcs_h, Wgwcs_l, Wcwcs_h, Wcwcs_l,
        Wgwwe_h, Wgwwe_l, Wcwwe_h, Wcwwe_l,
        Wghc_h, Wghc_l, Wchc_h, Wchc_l, Wghw_h, Wghw_l, Wchw_h, Wchw_l);
    cudaMemsetAsync(bar, 0, (2 * TC * 32 + 2 * TW * 8) * sizeof(int));
    k_sort<<<8, 256, U_ * sizeof(int)>>>(charseq_lens, U_, perm_c, iperm_c);
    k_sort<<<1, 256, B_ * sizeof(int)>>>(sentence_lens, B_, perm_w, iperm_w);

    // ---- char bi-GRU over unique word forms ----
    {
        int total = U_ * TC * CE;
        k_gather_char_sp<<<(total + 255) / 256, 256>>>(charseqs, char_emb, cAh, cAl, total);
    }
    k_mm_bias_t<false><<<dim3(8, (U_ * TC) / 128), 256>>>(cAh, cAl, Wgc_h, Wgc_l, bg_c, Xg_c, 1024, CE / 32);
    k_mm_bias_t<false><<<dim3(4, (U_ * TC) / 128), 256>>>(cAh, cAl, Wcc_h, Wcc_l, bc_c, Xc_c, 512, CE / 32);
    cudaMemsetAsync(Hc, 0, (size_t)2 * U_ * H * sizeof(float));
    cudaMemsetAsync(Hch, 0, (size_t)2 * U_ * H * sizeof(__nv_bfloat16));
    cudaMemsetAsync(Hcl, 0, (size_t)2 * U_ * H * sizeof(__nv_bfloat16));

    // char recurrence: persistent, length-sorted rows, per-mtile early exit
    k_char_rnn<<<128, 256>>>(Wghc_h, Wghc_l, Wchc_h, Wchc_l,
                             Xg_c, Xc_c, charseq_lens, perm_c,
                             Hc, Uc, Hch, Hcl, RHh, RHl, bar);

    // ---- word x-projections via unique-word factorization ----
    k_build_u<<<(U_ * 2 * H + 255) / 256, 256>>>(Hc, iperm_c, uAh, uAl);
    k_mm_bias_t<false><<<dim3(8, U_ / 128), 256>>>(uAh, uAl, Wgwcs_h, Wgwcs_l, bg_w, Pg, 1024, (2 * H) / 32);
    k_mm_bias_t<false><<<dim3(4, U_ / 128), 256>>>(uAh, uAl, Wcwcs_h, Wcwcs_l, bc_w, Pc, 512, (2 * H) / 32);
    k_combine<<<(B_ * TW * 384 + 255) / 256, 256>>>(charseq_ids, Pg, Pc, Xg_w, Xc_w);
    k_gather_we<<<(B_ * TW * WE + 255) / 256, 256>>>(word_ids, word_emb, weAh, weAl);
    k_mm_bias_t<true><<<dim3(8, (B_ * TW) / 128), 256>>>(weAh, weAl, Wgwwe_h, Wgwwe_l, bg_w, Xg_w, 1024, WE / 32);
    k_mm_bias_t<true><<<dim3(4, (B_ * TW) / 128), 256>>>(weAh, weAl, Wcwwe_h, Wcwwe_l, bc_w, Xc_w, 512, WE / 32);

    cudaMemsetAsync(Hw, 0, (size_t)2 * B_ * H * sizeof(float));
    cudaMemsetAsync(Hwh, 0, (size_t)2 * B_ * H * sizeof(__nv_bfloat16));
    cudaMemsetAsync(Hwl, 0, (size_t)2 * B_ * H * sizeof(__nv_bfloat16));

    // word recurrence: persistent, length-sorted rows, per-mtile early exit
    k_word_rnn<<<128, 128>>>(Wghw_h, Wghw_l, Wchw_h, Wchw_l,
                             Xg_w, Xc_w, sentence_lens, perm_w,
                             Hw, Uw, Hwh, Hwl, RHwh, RHwl, bar + 2 * TC * 32);

    // ---- head ----
    k_copy_states<<<(B_ * 2 * H + 255) / 256, 256>>>(Hw, iperm_w, states);
    k_sgemm_bias_s<<<dim3(1, B_ / 64), 256>>>(states, W1, b1, hidden, 64, 2 * H, 1);
    k_fc2<<<(B_ * 2 + 255) / 256, 256>>>(hidden, W2, b2, out);
}

// round 12
// speedup vs baseline: 1.0810x; 1.0810x over previous
#include <cuda_runtime.h>
#include <cuda_bf16.h>
#include <math.h>
#include <stdint.h>

// Problem constants
#define H   512
#define CE  128
#define WE  256
#define NC  256
#define U_  2048
#define TC  16
#define B_  256
#define TW  64
#define WD  (2*H + WE)   // 1280 word-input dim

// ---------------- scratch (device globals; allocation-free) ----------------
__device__ float g_Eg [(size_t)NC * 2 * H];     // char-proj tables (gates)
__device__ float g_Ec [(size_t)NC * H];         // char-proj tables (cand)
__device__ float g_Hc [(size_t)2 * U_ * H];
__device__ float g_Uc [(size_t)2 * U_ * H];
__device__ float g_Xg_w[(size_t)B_ * TW * 2 * H];
__device__ float g_Xc_w[(size_t)B_ * TW * H];
__device__ float g_Hw [(size_t)2 * B_ * H];
__device__ float g_Uw [(size_t)2 * B_ * H];
__device__ float g_Pg [(size_t)U_ * 2 * H];     // unique-word x-proj (gates)
__device__ float g_Pc [(size_t)U_ * H];         // unique-word x-proj (cand)
__device__ float g_states[(size_t)B_ * 2 * H];
__device__ float g_hidden[(size_t)B_ * 64];
// per-(step,phase,mtile) group-barrier counters: char 2*16*32, word 2*64*8
__device__ int   g_bar[2 * TC * 32 + 2 * TW * 8];

// split-bf16 A-operand images (tiled 128x32)
__device__ __align__(16) __nv_bfloat16 g_ceh[(size_t)NC * CE];       // char_emb split
__device__ __align__(16) __nv_bfloat16 g_cel[(size_t)NC * CE];
__device__ __align__(16) __nv_bfloat16 g_uAh[(size_t)U_ * 2 * H];
__device__ __align__(16) __nv_bfloat16 g_uAl[(size_t)U_ * 2 * H];
__device__ __align__(16) __nv_bfloat16 g_weAh[(size_t)B_ * TW * WE];
__device__ __align__(16) __nv_bfloat16 g_weAl[(size_t)B_ * TW * WE];
__device__ __align__(16) __nv_bfloat16 g_Hch[(size_t)2 * U_ * H];
__device__ __align__(16) __nv_bfloat16 g_Hcl[(size_t)2 * U_ * H];
__device__ __align__(16) __nv_bfloat16 g_RHh[(size_t)2 * U_ * H];
__device__ __align__(16) __nv_bfloat16 g_RHl[(size_t)2 * U_ * H];
__device__ __align__(16) __nv_bfloat16 g_Hwh[(size_t)2 * B_ * H];
__device__ __align__(16) __nv_bfloat16 g_Hwl[(size_t)2 * B_ * H];
__device__ __align__(16) __nv_bfloat16 g_RHwh[(size_t)2 * B_ * H];
__device__ __align__(16) __nv_bfloat16 g_RHwl[(size_t)2 * B_ * H];
// split-bf16 weights ([N,K] k-major tiled 128x32)
__device__ __align__(16) __nv_bfloat16 g_Wgc_h[(size_t)CE * 1024], g_Wgc_l[(size_t)CE * 1024];
__device__ __align__(16) __nv_bfloat16 g_Wcc_h[(size_t)CE * 512],  g_Wcc_l[(size_t)CE * 512];
__device__ __align__(16) __nv_bfloat16 g_Wgwcs_h[(size_t)1024 * 1024], g_Wgwcs_l[(size_t)1024 * 1024];
__device__ __align__(16) __nv_bfloat16 g_Wcwcs_h[(size_t)1024 * 512],  g_Wcwcs_l[(size_t)1024 * 512];
__device__ __align__(16) __nv_bfloat16 g_Wgwwe_h[(size_t)WE * 1024], g_Wgwwe_l[(size_t)WE * 1024];
__device__ __align__(16) __nv_bfloat16 g_Wcwwe_h[(size_t)WE * 512],  g_Wcwwe_l[(size_t)WE * 512];
__device__ __align__(16) __nv_bfloat16 g_Wghc_h[(size_t)H * 1024], g_Wghc_l[(size_t)H * 1024];
__device__ __align__(16) __nv_bfloat16 g_Wchc_h[(size_t)H * 512],  g_Wchc_l[(size_t)H * 512];
__device__ __align__(16) __nv_bfloat16 g_Wghw_h[(size_t)H * 1024], g_Wghw_l[(size_t)H * 1024];
__device__ __align__(16) __nv_bfloat16 g_Wchw_h[(size_t)H * 512],  g_Wchw_l[(size_t)H * 512];

// ---------------- helpers ----------------------------------------------------
__device__ __forceinline__ uint32_t smem_u32(const void* p) {
    uint32_t a;
    asm("{ .reg .u64 t; cvta.to.shared.u64 t, %1; cvt.u32.u64 %0, t; }" : "=r"(a) : "l"(p));
    return a;
}
__device__ __forceinline__ void split2(float v, __nv_bfloat16& h, __nv_bfloat16& l) {
    h = __float2bfloat16(v);
    l = __float2bfloat16(v - __bfloat162float(h));
}
__device__ __forceinline__ unsigned pack_bf(__nv_bfloat16 a, __nv_bfloat16 b) {
    unsigned short x = *(unsigned short*)&a, y = *(unsigned short*)&b;
    return (unsigned)x | ((unsigned)y << 16);
}
__device__ __forceinline__ size_t tiled_off(int row, int col, int NKt) {
    return ((size_t)((row >> 7) * NKt + (col >> 5)) * 128 + (row & 127)) * 32 + (col & 31);
}
__device__ __forceinline__ void ldm4(uint32_t r[4], uint32_t saddr) {
    asm volatile("ldmatrix.sync.aligned.m8n8.x4.shared.b16 {%0,%1,%2,%3}, [%4];"
                 : "=r"(r[0]), "=r"(r[1]), "=r"(r[2]), "=r"(r[3]) : "r"(saddr));
}
__device__ __forceinline__ void mma16816(float c[4], const uint32_t a[4], const uint32_t b[2]) {
    asm volatile(
        "mma.sync.aligned.m16n8k16.row.col.f32.bf16.bf16.f32 "
        "{%0,%1,%2,%3},{%4,%5,%6,%7},{%8,%9},{%0,%1,%2,%3};"
        : "+f"(c[0]), "+f"(c[1]), "+f"(c[2]), "+f"(c[3])
        : "r"(a[0]), "r"(a[1]), "r"(a[2]), "r"(a[3]), "r"(b[0]), "r"(b[1]));
}

// packed f32x2 (FFMA2) helpers for the scalar path
__device__ __forceinline__ unsigned long long pk2(float x) {
    unsigned long long d;
    unsigned u = __float_as_uint(x);
    asm("mov.b64 %0, {%1, %1};" : "=l"(d) : "r"(u));
    return d;
}
__device__ __forceinline__ void ffma2(unsigned long long& d,
                                      unsigned long long a,
                                      unsigned long long b) {
    asm("fma.rn.f32x2 %0, %1, %2, %0;" : "+l"(d) : "l"(a), "l"(b));
}
__device__ __forceinline__ float pick2(unsigned long long v, int half) {
    return __uint_as_float(half ? (unsigned)(v >> 32) : (unsigned)v);
}

// group barrier: n CTAs of one dependence group rendezvous on bar[idx]
__device__ __forceinline__ void grid_bar(int* bar, int idx, int n) {
    __syncthreads();
    if (threadIdx.x == 0) {
        __threadfence();
        atomicAdd(&bar[idx], 1);
        while (((volatile int*)bar)[idx] < n) __nanosleep(32);
        __threadfence();
    }
    __syncthreads();
}

// =============== split-bf16 mma.sync core: 128x128 tile, 256 thr ============
template<bool CG>
__device__ __forceinline__ void mma_core(
    const __nv_bfloat16* __restrict__ Ah, const __nv_bfloat16* __restrict__ Al,
    const __nv_bfloat16* __restrict__ Bh, const __nv_bfloat16* __restrict__ Bl,
    int NKt, int mt, int nt, float acc[4][4][4])
{
    __shared__ __align__(16) __nv_bfloat16 sA[2][128][40];
    __shared__ __align__(16) __nv_bfloat16 sB[2][128][40];
    const int tid = threadIdx.x, lane = tid & 31, warp = tid >> 5;
    const int wy = warp >> 2, wx = warp & 3;
    const int gq = lane >> 3, rr = lane & 7;
    uint4 pA[2][2], pB[2][2];

    auto gload = [&](int c) {
        #pragma unroll
        for (int i = 0; i < 2; i++) {
            int idx = tid + i * 256;
            int r = idx >> 2, c8 = idx & 3;
            size_t ta = ((size_t)(mt * NKt + c) * 128 + r) * 32 + c8 * 8;
            size_t tb = ((size_t)(nt * NKt + c) * 128 + r) * 32 + c8 * 8;
            if (CG) {
                pA[0][i] = __ldcg((const uint4*)(Ah + ta));
                pA[1][i] = __ldcg((const uint4*)(Al + ta));
            } else {
                pA[0][i] = *(const uint4*)(Ah + ta);
                pA[1][i] = *(const uint4*)(Al + ta);
            }
            pB[0][i] = *(const uint4*)(Bh + tb);
            pB[1][i] = *(const uint4*)(Bl + tb);
        }
    };
    auto sstore = [&]() {
        #pragma unroll
        for (int i = 0; i < 2; i++) {
            int idx = tid + i * 256;
            int r = idx >> 2, c8 = idx & 3;
            *(uint4*)&sA[0][r][c8 * 8] = pA[0][i];
            *(uint4*)&sA[1][r][c8 * 8] = pA[1][i];
            *(uint4*)&sB[0][r][c8 * 8] = pB[0][i];
            *(uint4*)&sB[1][r][c8 * 8] = pB[1][i];
        }
    };
    const uint32_t bAh = smem_u32(&sA[0][0][0]), bAl = smem_u32(&sA[1][0][0]);
    const uint32_t bBh = smem_u32(&sB[0][0][0]), bBl = smem_u32(&sB[1][0][0]);

    gload(0);
    for (int c = 0;;) {
        sstore();
        __syncthreads();
        int cn = c + 1;
        if (cn < NKt) gload(cn);
        #pragma unroll
        for (int s = 0; s < 2; s++) {
            uint32_t ah[4][4], al[4][4], bh[4][2], bl[4][2];
            #pragma unroll
            for (int mi = 0; mi < 4; mi++) {
                int row = wy * 64 + mi * 16 + (gq & 1) * 8 + rr;
                int col = s * 16 + (gq >> 1) * 8;
                uint32_t off = (uint32_t)(row * 40 + col) * 2;
                ldm4(ah[mi], bAh + off);
                ldm4(al[mi], bAl + off);
            }
            #pragma unroll
            for (int nb = 0; nb < 2; nb++) {
                int nrow = wx * 32 + nb * 16 + (gq >> 1) * 8 + rr;
                int col = s * 16 + (gq & 1) * 8;
                uint32_t off = (uint32_t)(nrow * 40 + col) * 2;
                uint32_t t0[4], t1[4];
                ldm4(t0, bBh + off);
                ldm4(t1, bBl + off);
                bh[nb * 2][0] = t0[0]; bh[nb * 2][1] = t0[1];
                bh[nb * 2 + 1][0] = t0[2]; bh[nb * 2 + 1][1] = t0[3];
                bl[nb * 2][0] = t1[0]; bl[nb * 2][1] = t1[1];
                bl[nb * 2 + 1][0] = t1[2]; bl[nb * 2 + 1][1] = t1[3];
            }
            #pragma unroll
            for (int mi = 0; mi < 4; mi++)
                #pragma unroll
                for (int ni = 0; ni < 4; ni++) {
                    mma16816(acc[mi][ni], ah[mi], bh[ni]);
                    mma16816(acc[mi][ni], ah[mi], bl[ni]);
                    mma16816(acc[mi][ni], al[mi], bh[ni]);
                }
        }
        __syncthreads();
        c = cn;
        if (c >= NKt) break;
    }
}

// =============== split-bf16 mma.sync core: 64x64 tile, 128 thr, CG A-loads ==
__device__ __forceinline__ void mma_core64cg(
    const __nv_bfloat16* __restrict__ Ah, const __nv_bfloat16* __restrict__ Al,
    const __nv_bfloat16* __restrict__ Bh, const __nv_bfloat16* __restrict__ Bl,
    int NKt, int bm, int bn, float acc[4][2][4])
{
    __shared__ __align__(16) __nv_bfloat16 sA[2][64][40];
    __shared__ __align__(16) __nv_bfloat16 sB[2][64][40];
    const int tid = threadIdx.x, lane = tid & 31, wx = tid >> 5;
    const int gq = lane >> 3, rr = lane & 7;
    uint4 pA[2][2], pB[2][2];
    const int mtb = bm >> 7, mro = bm & 127;
    const int ntb = bn >> 7, nro = bn & 127;

    auto gload = [&](int c) {
        #pragma unroll
        for (int i = 0; i < 2; i++) {
            int idx = tid + i * 128;
            int r = idx >> 2, c8 = idx & 3;
            size_t ta = ((size_t)(mtb * NKt + c) * 128 + mro + r) * 32 + c8 * 8;
            size_t tb = ((size_t)(ntb * NKt + c) * 128 + nro + r) * 32 + c8 * 8;
            pA[0][i] = __ldcg((const uint4*)(Ah + ta));
            pA[1][i] = __ldcg((const uint4*)(Al + ta));
            pB[0][i] = *(const uint4*)(Bh + tb);
            pB[1][i] = *(const uint4*)(Bl + tb);
        }
    };
    auto sstore = [&]() {
        #pragma unroll
        for (int i = 0; i < 2; i++) {
            int idx = tid + i * 128;
            int r = idx >> 2, c8 = idx & 3;
            *(uint4*)&sA[0][r][c8 * 8] = pA[0][i];
            *(uint4*)&sA[1][r][c8 * 8] = pA[1][i];
            *(uint4*)&sB[0][r][c8 * 8] = pB[0][i];
            *(uint4*)&sB[1][r][c8 * 8] = pB[1][i];
        }
    };
    const uint32_t bAh = smem_u32(&sA[0][0][0]), bAl = smem_u32(&sA[1][0][0]);
    const uint32_t bBh = smem_u32(&sB[0][0][0]), bBl = smem_u32(&sB[1][0][0]);

    gload(0);
    for (int c = 0;;) {
        sstore();
        __syncthreads();
        int cn = c + 1;
        if (cn < NKt) gload(cn);
        #pragma unroll
        for (int s = 0; s < 2; s++) {
            uint32_t ah[4][4], al[4][4], bh[2][2], bl[2][2];
            #pragma unroll
            for (int mi = 0; mi < 4; mi++) {
                int row = mi * 16 + (gq & 1) * 8 + rr;
                int col = s * 16 + (gq >> 1) * 8;
                uint32_t off = (uint32_t)(row * 40 + col) * 2;
                ldm4(ah[mi], bAh + off);
                ldm4(al[mi], bAl + off);
            }
            {
                int nrow = wx * 16 + (gq >> 1) * 8 + rr;
                int col = s * 16 + (gq & 1) * 8;
                uint32_t off = (uint32_t)(nrow * 40 + col) * 2;
                uint32_t t0[4], t1[4];
                ldm4(t0, bBh + off);
                ldm4(t1, bBl + off);
                bh[0][0] = t0[0]; bh[0][1] = t0[1];
                bh[1][0] = t0[2]; bh[1][1] = t0[3];
                bl[0][0] = t1[0]; bl[0][1] = t1[1];
                bl[1][0] = t1[2]; bl[1][1] = t1[3];
            }
            #pragma unroll
            for (int mi = 0; mi < 4; mi++)
                #pragma unroll
                for (int ni = 0; ni < 2; ni++) {
                    mma16816(acc[mi][ni], ah[mi], bh[ni]);
                    mma16816(acc[mi][ni], ah[mi], bl[ni]);
                    mma16816(acc[mi][ni], al[mi], bh[ni]);
                }
        }
        __syncthreads();
        c = cn;
        if (c >= NKt) break;
    }
}

// ---- GEMM + bias: C[M,Nd] fp32 = A@W + bias (ACC: C += A@W, no bias) ----
template<bool ACC>
__global__ void __launch_bounds__(256)
k_mm_bias_t(const __nv_bfloat16* __restrict__ Ah, const __nv_bfloat16* __restrict__ Al,
            const __nv_bfloat16* __restrict__ Bh, const __nv_bfloat16* __restrict__ Bl,
            const float* __restrict__ bias, float* __restrict__ C, int Nd, int NKt)
{
    float acc[4][4][4] = {};
    int nt = blockIdx.x, mt = blockIdx.y;
    mma_core<false>(Ah, Al, Bh, Bl, NKt, mt, nt, acc);
    int lane = threadIdx.x & 31, warp = threadIdx.x >> 5;
    int wy = warp >> 2, wx = warp & 3;
    int bm = mt * 128, bn = nt * 128;
    #pragma unroll
    for (int mi = 0; mi < 4; mi++) {
        #pragma unroll
        for (int ni = 0; ni < 4; ni++) {
            int n0 = bn + wx * 32 + ni * 8 + (lane & 3) * 2;
            int r0 = bm + wy * 64 + mi * 16 + (lane >> 2);
            float* p0 = C + (size_t)r0 * Nd + n0;
            float* p1 = C + (size_t)(r0 + 8) * Nd + n0;
            float2 v0, v1;
            if (ACC) {
                float2 o0 = *(float2*)p0, o1 = *(float2*)p1;
                v0 = {acc[mi][ni][0] + o0.x, acc[mi][ni][1] + o0.y};
                v1 = {acc[mi][ni][2] + o1.x, acc[mi][ni][3] + o1.y};
            } else {
                v0 = {acc[mi][ni][0] + bias[n0], acc[mi][ni][1] + bias[n0 + 1]};
                v1 = {acc[mi][ni][2] + bias[n0], acc[mi][ni][3] + bias[n0 + 1]};
            }
            *(float2*)p0 = v0;
            *(float2*)p1 = v1;
        }
    }
}

// ==================== PERSISTENT char bi-GRU (all 16 steps) =================
// X-projections come from tiny per-character tables Eg[256,1024], Ec[256,512]
// (L2-resident), indexed through charseqs — exact gather∘linear factorization.
__global__ void __launch_bounds__(256)
k_char_rnn(const __nv_bfloat16* __restrict__ Wgh_h, const __nv_bfloat16* __restrict__ Wgh_l,
           const __nv_bfloat16* __restrict__ Wch_h, const __nv_bfloat16* __restrict__ Wch_l,
           const float* __restrict__ Eg, const float* __restrict__ Ec,
           const int* __restrict__ charseqs, const int* __restrict__ lens,
           float* __restrict__ Hfp, float* __restrict__ Ug,
           __nv_bfloat16* __restrict__ Hh, __nv_bfloat16* __restrict__ Hl,
           __nv_bfloat16* __restrict__ RHh, __nv_bfloat16* __restrict__ RHl,
           int* __restrict__ bar)
{
    const int lane = threadIdx.x & 31, warp = threadIdx.x >> 5;
    const int wy = warp >> 2, wx = warp & 3;
    const int Nseq = U_, T = TC;
    const int mt = blockIdx.x >> 2;
    const int sub = blockIdx.x & 3;
    const int bm = mt * 128;

    #pragma unroll 1
    for (int t = 0; t < TC; t++) {
        // ---------- gates: 2 n-tiles per CTA, same mt ----------
        #pragma unroll 1
        for (int rep = 0; rep < 2; rep++) {
            int nt = sub * 2 + rep;
            float acc[4][4][4] = {};
            mma_core<true>(Hh, Hl, Wgh_h, Wgh_l, H / 32, mt, nt, acc);
            int bn = nt * 128;
            bool isR = (bn + 128 <= H);
            #pragma unroll
            for (int mi = 0; mi < 4; mi++) {
                #pragma unroll
                for (int hh = 0; hh < 2; hh++) {
                    int r = bm + wy * 64 + mi * 16 + (lane >> 2) + hh * 8;
                    int dir = (r >= Nseq);
                    int n = dir ? r - Nseq : r;
                    int len = lens[n];
                    int te = dir ? max(0, min(len - 1 - t, T - 1)) : t;
                    int id = charseqs[n * T + te];
                    const float* xg = Eg + (size_t)id * (2 * H);
                    #pragma unroll
                    for (int ni = 0; ni < 4; ni++) {
                        int c0 = bn + wx * 32 + ni * 8 + (lane & 3) * 2;
                        float a0 = acc[mi][ni][hh * 2 + 0];
                        float a1 = acc[mi][ni][hh * 2 + 1];
                        float g0 = 1.f / (1.f + __expf(-(xg[c0] + a0)));
                        float g1 = 1.f / (1.f + __expf(-(xg[c0 + 1] + a1)));
                        if (isR) {
                            float2 hv = __ldcg((const float2*)(Hfp + (size_t)r * H + c0));
                            float rh0 = g0 * hv.x, rh1 = g1 * hv.y;
                            __nv_bfloat16 h0, l0, h1, l1;
                            split2(rh0, h0, l0);
                            split2(rh1, h1, l1);
                            size_t o = tiled_off(r, c0, H / 32);
                            __stcg((unsigned*)(RHh + o), pack_bf(h0, h1));
                            __stcg((unsigned*)(RHl + o), pack_bf(l0, l1));
                        } else {
                            float2 uv = {g0, g1};
                            __stcg((float2*)(Ug + (size_t)r * H + (c0 - H)), uv);
                        }
                    }
                }
            }
        }
        grid_bar(bar, 2 * t * 32 + mt, 4);

        // ---------- cand: 1 n-tile per CTA, same mt ----------
        {
            int nt = sub;
            float acc[4][4][4] = {};
            mma_core<true>(RHh, RHl, Wch_h, Wch_l, H / 32, mt, nt, acc);
            int bn = nt * 128;
            #pragma unroll
            for (int mi = 0; mi < 4; mi++) {
                #pragma unroll
                for (int hh = 0; hh < 2; hh++) {
                    int r = bm + wy * 64 + mi * 16 + (lane >> 2) + hh * 8;
                    int dir = (r >= Nseq);
                    int n = dir ? r - Nseq : r;
                    int len = lens[n];
                    if (t >= len) continue;   // frozen
                    int te = dir ? max(0, min(len - 1 - t, T - 1)) : t;
                    int id = charseqs[n * T + te];
                    const float* xc = Ec + (size_t)id * H;
                    #pragma unroll
                    for (int ni = 0; ni < 4; ni++) {
                        int c0 = bn + wx * 32 + ni * 8 + (lane & 3) * 2;
                        float cc0 = tanhf(xc[c0] + acc[mi][ni][hh * 2 + 0]);
                        float cc1 = tanhf(xc[c0 + 1] + acc[mi][ni][hh * 2 + 1]);
                        float2 hv = __ldcg((const float2*)(Hfp + (size_t)r * H + c0));
                        float2 uv = __ldcg((const float2*)(Ug + (size_t)r * H + c0));
                        float hn0 = uv.x * hv.x + (1.f - uv.x) * cc0;
                        float hn1 = uv.y * hv.y + (1.f - uv.y) * cc1;
                        float2 hw = {hn0, hn1};
                        __stcg((float2*)(Hfp + (size_t)r * H + c0), hw);
                        __nv_bfloat16 h0, l0, h1, l1;
                        split2(hn0, h0, l0);
                        split2(hn1, h1, l1);
                        size_t o = tiled_off(r, c0, H / 32);
                        __stcg((unsigned*)(Hh + o), pack_bf(h0, h1));
                        __stcg((unsigned*)(Hl + o), pack_bf(l0, l1));
                    }
                }
            }
        }
        grid_bar(bar, (2 * t + 1) * 32 + mt, 4);
    }
}

// ==================== PERSISTENT word bi-GRU (all 64 steps) =================
__global__ void __launch_bounds__(128)
k_word_rnn(const __nv_bfloat16* __restrict__ Wgh_h, const __nv_bfloat16* __restrict__ Wgh_l,
           const __nv_bfloat16* __restrict__ Wch_h, const __nv_bfloat16* __restrict__ Wch_l,
           const float* __restrict__ Xg, const float* __restrict__ Xc,
           const int* __restrict__ lens,
           float* __restrict__ Hfp, float* __restrict__ Ug,
           __nv_bfloat16* __restrict__ Hh, __nv_bfloat16* __restrict__ Hl,
           __nv_bfloat16* __restrict__ RHh, __nv_bfloat16* __restrict__ RHl,
           int* __restrict__ bar)
{
    const int cta = blockIdx.x;
    const int mtile = cta >> 4, ntile = cta & 15;
    const int bm = mtile * 64;
    const int lane = threadIdx.x & 31, wx = threadIdx.x >> 5;
    const int Nseq = B_, T = TW;

    #pragma unroll 1
    for (int t = 0; t < TW; t++) {
        // ---------- gates ----------
        {
            float acc[4][2][4] = {};
            int bn = ntile * 64;
            mma_core64cg(Hh, Hl, Wgh_h, Wgh_l, H / 32, bm, bn, acc);
            bool isR = (bn + 64 <= H);
            #pragma unroll
            for (int mi = 0; mi < 4; mi++) {
                #pragma unroll
                for (int hh = 0; hh < 2; hh++) {
                    int r = bm + mi * 16 + (lane >> 2) + hh * 8;
                    int dir = (r >= Nseq);
                    int n = dir ? r - Nseq : r;
                    int len = lens[n];
                    int te = dir ? max(0, min(len - 1 - t, T - 1)) : t;
                    const float* xg = Xg + ((size_t)n * T + te) * (2 * H);
                    #pragma unroll
                    for (int ni = 0; ni < 2; ni++) {
                        int c0 = bn + wx * 16 + ni * 8 + (lane & 3) * 2;
                        float a0 = acc[mi][ni][hh * 2 + 0];
                        float a1 = acc[mi][ni][hh * 2 + 1];
                        float g0 = 1.f / (1.f + __expf(-(xg[c0] + a0)));
                        float g1 = 1.f / (1.f + __expf(-(xg[c0 + 1] + a1)));
                        if (isR) {
                            float2 hv = __ldcg((const float2*)(Hfp + (size_t)r * H + c0));
                            float rh0 = g0 * hv.x, rh1 = g1 * hv.y;
                            __nv_bfloat16 h0, l0, h1, l1;
                            split2(rh0, h0, l0);
                            split2(rh1, h1, l1);
                            size_t o = tiled_off(r, c0, H / 32);
                            __stcg((unsigned*)(RHh + o), pack_bf(h0, h1));
                            __stcg((unsigned*)(RHl + o), pack_bf(l0, l1));
                        } else {
                            float2 uv = {g0, g1};
                            __stcg((float2*)(Ug + (size_t)r * H + (c0 - H)), uv);
                        }
                    }
                }
            }
        }
        grid_bar(bar, 2 * t * 8 + mtile, 16);

        // ---------- cand ----------
        if (ntile < 8) {
            float acc[4][2][4] = {};
            int bn = ntile * 64;
            mma_core64cg(RHh, RHl, Wch_h, Wch_l, H / 32, bm, bn, acc);
            #pragma unroll
            for (int mi = 0; mi < 4; mi++) {
                #pragma unroll
                for (int hh = 0; hh < 2; hh++) {
                    int r = bm + mi * 16 + (lane >> 2) + hh * 8;
                    int dir = (r >= Nseq);
                    int n = dir ? r - Nseq : r;
                    int len = lens[n];
                    if (t >= len) continue;   // frozen
                    int te = dir ? max(0, min(len - 1 - t, T - 1)) : t;
                    const float* xc = Xc + ((size_t)n * T + te) * H;
                    #pragma unroll
                    for (int ni = 0; ni < 2; ni++) {
                        int c0 = bn + wx * 16 + ni * 8 + (lane & 3) * 2;
                        float cc0 = tanhf(xc[c0] + acc[mi][ni][hh * 2 + 0]);
                        float cc1 = tanhf(xc[c0 + 1] + acc[mi][ni][hh * 2 + 1]);
                        float2 hv = __ldcg((const float2*)(Hfp + (size_t)r * H + c0));
                        float2 uv = __ldcg((const float2*)(Ug + (size_t)r * H + c0));
                        float hn0 = uv.x * hv.x + (1.f - uv.x) * cc0;
                        float hn1 = uv.y * hv.y + (1.f - uv.y) * cc1;
                        float2 hw = {hn0, hn1};
                        __stcg((float2*)(Hfp + (size_t)r * H + c0), hw);
                        __nv_bfloat16 h0, l0, h1, l1;
                        split2(hn0, h0, l0);
                        split2(hn1, h1, l1);
                        size_t o = tiled_off(r, c0, H / 32);
                        __stcg((unsigned*)(Hh + o), pack_bf(h0, h1));
                        __stcg((unsigned*)(Hl + o), pack_bf(l0, l1));
                    }
                }
            }
        }
        grid_bar(bar, (2 * t + 1) * 8 + mtile, 16);
    }
}

// ---- fused one-time weight split (all 10 segments in one launch) ----
__device__ __forceinline__ void prep1(const float* W, int idx, int Nd, int NKt,
                                      __nv_bfloat16* Bh, __nv_bfloat16* Bl) {
    int k = idx / Nd, n = idx % Nd;
    __nv_bfloat16 h, l;
    split2(W[idx], h, l);
    size_t off = ((size_t)((n >> 7) * NKt + (k >> 5)) * 128 + (n & 127)) * 32 + (k & 31);
    Bh[off] = h; Bl[off] = l;
}

#define Q1 (CE * 1024)
#define Q2 (Q1 + CE * 512)
#define Q3 (Q2 + 1024 * 1024)
#define Q4 (Q3 + 1024 * 512)
#define Q5 (Q4 + WE * 1024)
#define Q6 (Q5 + WE * 512)
#define Q7 (Q6 + H * 1024)
#define Q8 (Q7 + H * 512)
#define Q9 (Q8 + H * 1024)
#define Q10 (Q9 + H * 512)

__global__ void k_prep_all(const float* __restrict__ Wg_c, const float* __restrict__ Wc_c,
                           const float* __restrict__ Wg_w, const float* __restrict__ Wc_w,
                           __nv_bfloat16* Wgc_h, __nv_bfloat16* Wgc_l,
                           __nv_bfloat16* Wcc_h, __nv_bfloat16* Wcc_l,
                           __nv_bfloat16* Wgwcs_h, __nv_bfloat16* Wgwcs_l,
                           __nv_bfloat16* Wcwcs_h, __nv_bfloat16* Wcwcs_l,
                           __nv_bfloat16* Wgwwe_h, __nv_bfloat16* Wgwwe_l,
                           __nv_bfloat16* Wcwwe_h, __nv_bfloat16* Wcwwe_l,
                           __nv_bfloat16* Wghc_h, __nv_bfloat16* Wghc_l,
                           __nv_bfloat16* Wchc_h, __nv_bfloat16* Wchc_l,
                           __nv_bfloat16* Wghw_h, __nv_bfloat16* Wghw_l,
                           __nv_bfloat16* Wchw_h, __nv_bfloat16* Wchw_l) {
    int i = blockIdx.x * blockDim.x + threadIdx.x;
    if (i < Q1)      prep1(Wg_c, i, 1024, CE / 32, Wgc_h, Wgc_l);
    else if (i < Q2) prep1(Wc_c, i - Q1, 512, CE / 32, Wcc_h, Wcc_l);
    else if (i < Q3) prep1(Wg_w, i - Q2, 1024, 1024 / 32, Wgwcs_h, Wgwcs_l);
    else if (i < Q4) prep1(Wc_w, i - Q3, 512, 1024 / 32, Wcwcs_h, Wcwcs_l);
    else if (i < Q5) prep1(Wg_w + (size_t)1024 * 1024, i - Q4, 1024, WE / 32, Wgwwe_h, Wgwwe_l);
    else if (i < Q6) prep1(Wc_w + (size_t)1024 * 512, i - Q5, 512, WE / 32, Wcwwe_h, Wcwwe_l);
    else if (i < Q7) prep1(Wg_c + (size_t)CE * 1024, i - Q6, 1024, H / 32, Wghc_h, Wghc_l);
    else if (i < Q8) prep1(Wc_c + (size_t)CE * 512, i - Q7, 512, H / 32, Wchc_h, Wchc_l);
    else if (i < Q9) prep1(Wg_w + (size_t)WD * 1024, i - Q8, 1024, H / 32, Wghw_h, Wghw_l);
    else if (i < Q10) prep1(Wc_w + (size_t)WD * 512, i - Q9, 512, H / 32, Wchw_h, Wchw_l);
}

// ---- split char_emb [NC x CE] into tiled image ------------------------------
__global__ void k_split_ce(const float* __restrict__ ce,
                           __nv_bfloat16* __restrict__ Ah,
                           __nv_bfloat16* __restrict__ Al) {
    int i = blockIdx.x * blockDim.x + threadIdx.x;
    if (i >= NC * CE) return;
    int r = i >> 7, c = i & (CE - 1);
    __nv_bfloat16 h, l;
    split2(ce[i], h, l);
    size_t off = tiled_off(r, c, CE / 32);
    Ah[off] = h; Al[off] = l;
}

// build unique-word concat-state split image [U x 2H] from final Hc
__global__ void k_build_u(const float* __restrict__ Hc,
                          __nv_bfloat16* __restrict__ Ah,
                          __nv_bfloat16* __restrict__ Al) {
    int i = blockIdx.x * blockDim.x + threadIdx.x;
    if (i >= U_ * 2 * H) return;
    int c = i & (2 * H - 1);
    int u = i >> 10;
    float v = (c < H) ? Hc[(size_t)u * H + c] : Hc[(size_t)(U_ + u) * H + (c - H)];
    __nv_bfloat16 h, l;
    split2(v, h, l);
    size_t off = tiled_off(u, c, (2 * H) / 32);
    Ah[off] = h; Al[off] = l;
}

// gather word embeddings only (WE cols) into split image [B*TW x WE]
__global__ void k_gather_we(const int* __restrict__ wids,
                            const float* __restrict__ word_emb,
                            __nv_bfloat16* __restrict__ Ah,
                            __nv_bfloat16* __restrict__ Al) {
    int i = blockIdx.x * blockDim.x + threadIdx.x;
    if (i >= B_ * TW * WE) return;
    int c = i & (WE - 1);
    int bt = i >> 8;
    float v = word_emb[(size_t)wids[bt] * WE + c];
    __nv_bfloat16 h, l;
    split2(v, h, l);
    size_t off = tiled_off(bt, c, WE / 32);
    Ah[off] = h; Al[off] = l;
}

// scatter unique projections to per-token X buffers (bias already in P)
__global__ void k_combine(const int* __restrict__ cids,
                          const float* __restrict__ Pg, const float* __restrict__ Pc,
                          float* __restrict__ Xg, float* __restrict__ Xc) {
    int i = blockIdx.x * blockDim.x + threadIdx.x;
    const int total = B_ * TW * 384;
    if (i >= total) return;
    int bt = i / 384, j = i % 384;
    int u = cids[bt];
    if (j < 256)
        ((float4*)Xg)[(size_t)bt * 256 + j] = ((const float4*)Pg)[(size_t)u * 256 + j];
    else
        ((float4*)Xc)[(size_t)bt * 128 + (j - 256)] = ((const float4*)Pc)[(size_t)u * 128 + (j - 256)];
}

// ============ small 64x64 / 4x4 FFMA2 core (head) ===========================
__device__ __forceinline__ void gemm64_2(const float* __restrict__ A,
                                         const float* __restrict__ Bm,
                                         int K, int N, int bm, int bn,
                                         unsigned long long acc[4][2]) {
    __shared__ float As[2][16][64];
    __shared__ float Bs[2][16][64];
    const int tid = threadIdx.x;
    const int tx = tid & 15;
    const int ty = tid >> 4;
    float4 aR, bR;
    auto loadA = [&](int k0) {
        int r = tid >> 2, c4 = tid & 3;
        aR = *(const float4*)(A + (size_t)(bm + r) * K + k0 + c4 * 4);
    };
    auto loadB = [&](int k0) {
        int kr = tid >> 4, c4 = tid & 15;
        bR = *(const float4*)(Bm + (size_t)(k0 + kr) * N + bn + c4 * 4);
    };
    auto stage = [&](int buf) {
        int r = tid >> 2, c4 = tid & 3;
        As[buf][c4 * 4 + 0][r] = aR.x;
        As[buf][c4 * 4 + 1][r] = aR.y;
        As[buf][c4 * 4 + 2][r] = aR.z;
        As[buf][c4 * 4 + 3][r] = aR.w;
        int kr = tid >> 4, cb = tid & 15;
        *(float4*)&Bs[buf][kr][cb * 4] = bR;
    };
    loadA(0); loadB(0);
    stage(0);
    __syncthreads();
    int buf = 0;
    for (int k0 = 0;;) {
        int kn = k0 + 16;
        if (kn < K) { loadA(kn); loadB(kn); }
        #pragma unroll
        for (int k = 0; k < 16; k++) {
            float4 a = *(const float4*)&As[buf][k][ty * 4];
            ulonglong2 bp = *(const ulonglong2*)&Bs[buf][k][tx * 4];
            float av[4] = {a.x, a.y, a.z, a.w};
            #pragma unroll
            for (int i = 0; i < 4; i++) {
                unsigned long long ad = pk2(av[i]);
                ffma2(acc[i][0], ad, bp.x);
                ffma2(acc[i][1], ad, bp.y);
            }
        }
        if (kn >= K) break;
        stage(buf ^ 1);
        __syncthreads();
        buf ^= 1;
        k0 = kn;
    }
}

__global__ __launch_bounds__(256)
void k_sgemm_bias_s(const float* __restrict__ A, const float* __restrict__ Bm,
                    const float* __restrict__ bias, float* __restrict__ C,
                    int N, int K, int act) {
    unsigned long long acc[4][2] = {};
    int bm = blockIdx.y * 64, bn = blockIdx.x * 64;
    gemm64_2(A, Bm, K, N, bm, bn, acc);
    const int tx = threadIdx.x & 15, ty = threadIdx.x >> 4;
    #pragma unroll
    for (int i = 0; i < 4; i++) {
        int r = bm + ty * 4 + i;
        #pragma unroll
        for (int q = 0; q < 4; q++) {
            int c = bn + tx * 4 + q;
            float v = pick2(acc[i][q >> 1], q & 1) + bias[c];
            if (act) v = v > 0.f ? v : 0.2f * v;
            C[(size_t)r * N + c] = v;
        }
    }
}

// ---------------- misc small kernels -----------------------------------------
__global__ void k_copy_states(const float* __restrict__ Hw, float* __restrict__ out) {
    int i = blockIdx.x * blockDim.x + threadIdx.x;
    if (i >= B_ * 2 * H) return;
    int c = i % (2 * H);
    int b = i / (2 * H);
    out[i] = (c < H) ? Hw[(size_t)b * H + c] : Hw[(size_t)(B_ + b) * H + (c - H)];
}

__global__ void k_fc2(const float* __restrict__ hidden, const float* __restrict__ W2,
                      const float* __restrict__ b2, float* __restrict__ out) {
    int i = blockIdx.x * blockDim.x + threadIdx.x;
    if (i >= B_ * 2) return;
    int b = i >> 1, j = i & 1;
    float s = b2[j];
    #pragma unroll
    for (int k = 0; k < 64; k++) s = fmaf(hidden[b * 64 + k], W2[k * 2 + j], s);
    out[i] = s;
}

// ---------------- host orchestration ----------------------------------------
extern "C" void kernel_launch(void* const* d_in, const int* in_sizes, int n_in,
                              void* d_out, int out_size) {
    const int*   charseqs      = (const int*)d_in[0];
    const int*   charseq_lens  = (const int*)d_in[1];
    const int*   charseq_ids   = (const int*)d_in[2];
    const int*   word_ids      = (const int*)d_in[3];
    const int*   sentence_lens = (const int*)d_in[4];
    const float* char_emb      = (const float*)d_in[5];
    const float* word_emb      = (const float*)d_in[6];
    const float* Wg_c = (const float*)d_in[7];
    const float* bg_c = (const float*)d_in[8];
    const float* Wc_c = (const float*)d_in[9];
    const float* bc_c = (const float*)d_in[10];
    const float* Wg_w = (const float*)d_in[11];
    const float* bg_w = (const float*)d_in[12];
    const float* Wc_w = (const float*)d_in[13];
    const float* bc_w = (const float*)d_in[14];
    const float* W1   = (const float*)d_in[15];
    const float* b1   = (const float*)d_in[16];
    const float* W2   = (const float*)d_in[17];
    const float* b2   = (const float*)d_in[18];
    float* out = (float*)d_out;

    float *Eg, *Ec, *Hc, *Uc, *Xg_w, *Xc_w, *Hw, *Uw, *Pg, *Pc, *states, *hidden;
    int* bar;
    __nv_bfloat16 *ceh, *cel, *uAh, *uAl, *weAh, *weAl, *Hch, *Hcl, *RHh, *RHl;
    __nv_bfloat16 *Hwh, *Hwl, *RHwh, *RHwl;
    __nv_bfloat16 *Wgc_h, *Wgc_l, *Wcc_h, *Wcc_l;
    __nv_bfloat16 *Wgwcs_h, *Wgwcs_l, *Wcwcs_h, *Wcwcs_l;
    __nv_bfloat16 *Wgwwe_h, *Wgwwe_l, *Wcwwe_h, *Wcwwe_l;
    __nv_bfloat16 *Wghc_h, *Wghc_l, *Wchc_h, *Wchc_l, *Wghw_h, *Wghw_l, *Wchw_h, *Wchw_l;
    cudaGetSymbolAddress((void**)&Eg,     g_Eg);
    cudaGetSymbolAddress((void**)&Ec,     g_Ec);
    cudaGetSymbolAddress((void**)&Hc,     g_Hc);
    cudaGetSymbolAddress((void**)&Uc,     g_Uc);
    cudaGetSymbolAddress((void**)&Xg_w,   g_Xg_w);
    cudaGetSymbolAddress((void**)&Xc_w,   g_Xc_w);
    cudaGetSymbolAddress((void**)&Hw,     g_Hw);
    cudaGetSymbolAddress((void**)&Uw,     g_Uw);
    cudaGetSymbolAddress((void**)&Pg,     g_Pg);
    cudaGetSymbolAddress((void**)&Pc,     g_Pc);
    cudaGetSymbolAddress((void**)&states, g_states);
    cudaGetSymbolAddress((void**)&hidden, g_hidden);
    cudaGetSymbolAddress((void**)&bar,    g_bar);
    cudaGetSymbolAddress((void**)&ceh, g_ceh);
    cudaGetSymbolAddress((void**)&cel, g_cel);
    cudaGetSymbolAddress((void**)&uAh, g_uAh);
    cudaGetSymbolAddress((void**)&uAl, g_uAl);
    cudaGetSymbolAddress((void**)&weAh, g_weAh);
    cudaGetSymbolAddress((void**)&weAl, g_weAl);
    cudaGetSymbolAddress((void**)&Hch, g_Hch);
    cudaGetSymbolAddress((void**)&Hcl, g_Hcl);
    cudaGetSymbolAddress((void**)&RHh, g_RHh);
    cudaGetSymbolAddress((void**)&RHl, g_RHl);
    cudaGetSymbolAddress((void**)&Hwh, g_Hwh);
    cudaGetSymbolAddress((void**)&Hwl, g_Hwl);
    cudaGetSymbolAddress((void**)&RHwh, g_RHwh);
    cudaGetSymbolAddress((void**)&RHwl, g_RHwl);
    cudaGetSymbolAddress((void**)&Wgc_h, g_Wgc_h);
    cudaGetSymbolAddress((void**)&Wgc_l, g_Wgc_l);
    cudaGetSymbolAddress((void**)&Wcc_h, g_Wcc_h);
    cudaGetSymbolAddress((void**)&Wcc_l, g_Wcc_l);
    cudaGetSymbolAddress((void**)&Wgwcs_h, g_Wgwcs_h);
    cudaGetSymbolAddress((void**)&Wgwcs_l, g_Wgwcs_l);
    cudaGetSymbolAddress((void**)&Wcwcs_h, g_Wcwcs_h);
    cudaGetSymbolAddress((void**)&Wcwcs_l, g_Wcwcs_l);
    cudaGetSymbolAddress((void**)&Wgwwe_h, g_Wgwwe_h);
    cudaGetSymbolAddress((void**)&Wgwwe_l, g_Wgwwe_l);
    cudaGetSymbolAddress((void**)&Wcwwe_h, g_Wcwwe_h);
    cudaGetSymbolAddress((void**)&Wcwwe_l, g_Wcwwe_l);
    cudaGetSymbolAddress((void**)&Wghc_h, g_Wghc_h);
    cudaGetSymbolAddress((void**)&Wghc_l, g_Wghc_l);
    cudaGetSymbolAddress((void**)&Wchc_h, g_Wchc_h);
    cudaGetSymbolAddress((void**)&Wchc_l, g_Wchc_l);
    cudaGetSymbolAddress((void**)&Wghw_h, g_Wghw_h);
    cudaGetSymbolAddress((void**)&Wghw_l, g_Wghw_l);
    cudaGetSymbolAddress((void**)&Wchw_h, g_Wchw_h);
    cudaGetSymbolAddress((void**)&Wchw_l, g_Wchw_l);

    // ---- one fused weight-split launch ----
    k_prep_all<<<(Q10 + 255) / 256, 256>>>(Wg_c, Wc_c, Wg_w, Wc_w,
        Wgc_h, Wgc_l, Wcc_h, Wcc_l,
        Wgwcs_h, Wgwcs_l, Wcwcs_h, Wcwcs_l,
        Wgwwe_h, Wgwwe_l, Wcwwe_h, Wcwwe_l,
        Wghc_h, Wghc_l, Wchc_h, Wchc_l, Wghw_h, Wghw_l, Wchw_h, Wchw_l);
    cudaMemsetAsync(bar, 0, (2 * TC * 32 + 2 * TW * 8) * sizeof(int));

    // ---- per-character x-proj tables: Eg = char_emb@Wxg + bg, Ec likewise ----
    k_split_ce<<<(NC * CE + 255) / 256, 256>>>(char_emb, ceh, cel);
    k_mm_bias_t<false><<<dim3(8, NC / 128), 256>>>(ceh, cel, Wgc_h, Wgc_l, bg_c, Eg, 1024, CE / 32);
    k_mm_bias_t<false><<<dim3(4, NC / 128), 256>>>(ceh, cel, Wcc_h, Wcc_l, bc_c, Ec, 512, CE / 32);
    cudaMemsetAsync(Hc, 0, (size_t)2 * U_ * H * sizeof(float));
    cudaMemsetAsync(Hch, 0, (size_t)2 * U_ * H * sizeof(__nv_bfloat16));
    cudaMemsetAsync(Hcl, 0, (size_t)2 * U_ * H * sizeof(__nv_bfloat16));

    // char recurrence: ONE persistent kernel, per-mtile group barriers,
    // x-projections read from L2-resident per-character tables
    k_char_rnn<<<128, 256>>>(Wghc_h, Wghc_l, Wchc_h, Wchc_l,
                             Eg, Ec, charseqs, charseq_lens,
                             Hc, Uc, Hch, Hcl, RHh, RHl, bar);

    // ---- word x-projections via unique-word factorization ----
    k_build_u<<<(U_ * 2 * H + 255) / 256, 256>>>(Hc, uAh, uAl);
    k_mm_bias_t<false><<<dim3(8, U_ / 128), 256>>>(uAh, uAl, Wgwcs_h, Wgwcs_l, bg_w, Pg, 1024, (2 * H) / 32);
    k_mm_bias_t<false><<<dim3(4, U_ / 128), 256>>>(uAh, uAl, Wcwcs_h, Wcwcs_l, bc_w, Pc, 512, (2 * H) / 32);
    k_combine<<<(B_ * TW * 384 + 255) / 256, 256>>>(charseq_ids, Pg, Pc, Xg_w, Xc_w);
    k_gather_we<<<(B_ * TW * WE + 255) / 256, 256>>>(word_ids, word_emb, weAh, weAl);
    k_mm_bias_t<true><<<dim3(8, (B_ * TW) / 128), 256>>>(weAh, weAl, Wgwwe_h, Wgwwe_l, bg_w, Xg_w, 1024, WE / 32);
    k_mm_bias_t<true><<<dim3(4, (B_ * TW) / 128), 256>>>(weAh, weAl, Wcwwe_h, Wcwwe_l, bc_w, Xc_w, 512, WE / 32);

    cudaMemsetAsync(Hw, 0, (size_t)2 * B_ * H * sizeof(float));
    cudaMemsetAsync(Hwh, 0, (size_t)2 * B_ * H * sizeof(__nv_bfloat16));
    cudaMemsetAsync(Hwl, 0, (size_t)2 * B_ * H * sizeof(__nv_bfloat16));

    // word recurrence: ONE persistent kernel, per-mtile group barriers
    k_word_rnn<<<128, 128>>>(Wghw_h, Wghw_l, Wchw_h, Wchw_l,
                             Xg_w, Xc_w, sentence_lens,
                             Hw, Uw, Hwh, Hwl, RHwh, RHwl, bar + 2 * TC * 32);

    // ---- head ----
    k_copy_states<<<(B_ * 2 * H + 255) / 256, 256>>>(Hw, states);
    k_sgemm_bias_s<<<dim3(1, B_ / 64), 256>>>(states, W1, b1, hidden, 64, 2 * H, 1);
    k_fc2<<<(B_ * 2 + 255) / 256, 256>>>(hidden, W2, b2, out);
}

// round 13
// speedup vs baseline: 1.0819x; 1.0008x over previous
#include <cuda_runtime.h>
#include <cuda_bf16.h>
#include <math.h>
#include <stdint.h>

// Problem constants
#define H   512
#define CE  128
#define WE  256
#define NC  256
#define U_  2048
#define TC  16
#define B_  256
#define TW  64
#define WD  (2*H + WE)   // 1280 word-input dim

// ---------------- scratch (device globals; allocation-free) ----------------
__device__ float g_Eg [(size_t)NC * 2 * H];     // char-proj tables (gates)
__device__ float g_Ec [(size_t)NC * H];         // char-proj tables (cand)
__device__ float g_Hc [(size_t)2 * U_ * H];
__device__ float g_Uc [(size_t)2 * U_ * H];
__device__ float g_Xg_w[(size_t)B_ * TW * 2 * H];
__device__ float g_Xc_w[(size_t)B_ * TW * H];
__device__ float g_Hw [(size_t)2 * B_ * H];
__device__ float g_Uw [(size_t)2 * B_ * H];
__device__ float g_Pg [(size_t)U_ * 2 * H];     // unique-word x-proj (gates)
__device__ float g_Pc [(size_t)U_ * H];         // unique-word x-proj (cand)
__device__ float g_states[(size_t)B_ * 2 * H];
__device__ float g_hidden[(size_t)B_ * 64];
// per-(step,phase,mtile) group-barrier counters: char 2*16*32, word 2*64*8
__device__ int   g_bar[2 * TC * 32 + 2 * TW * 8];

// split-bf16 A-operand images (tiled 128x32)
__device__ __align__(16) __nv_bfloat16 g_ceh[(size_t)NC * CE];       // char_emb split
__device__ __align__(16) __nv_bfloat16 g_cel[(size_t)NC * CE];
__device__ __align__(16) __nv_bfloat16 g_uAh[(size_t)U_ * 2 * H];
__device__ __align__(16) __nv_bfloat16 g_uAl[(size_t)U_ * 2 * H];
__device__ __align__(16) __nv_bfloat16 g_weAh[(size_t)B_ * TW * WE];
__device__ __align__(16) __nv_bfloat16 g_weAl[(size_t)B_ * TW * WE];
__device__ __align__(16) __nv_bfloat16 g_Hch[(size_t)2 * U_ * H];
__device__ __align__(16) __nv_bfloat16 g_Hcl[(size_t)2 * U_ * H];
__device__ __align__(16) __nv_bfloat16 g_RHh[(size_t)2 * U_ * H];
__device__ __align__(16) __nv_bfloat16 g_RHl[(size_t)2 * U_ * H];
__device__ __align__(16) __nv_bfloat16 g_Hwh[(size_t)2 * B_ * H];
__device__ __align__(16) __nv_bfloat16 g_Hwl[(size_t)2 * B_ * H];
__device__ __align__(16) __nv_bfloat16 g_RHwh[(size_t)2 * B_ * H];
__device__ __align__(16) __nv_bfloat16 g_RHwl[(size_t)2 * B_ * H];
// split-bf16 weights ([N,K] k-major tiled 128x32)
__device__ __align__(16) __nv_bfloat16 g_Wgc_h[(size_t)CE * 1024], g_Wgc_l[(size_t)CE * 1024];
__device__ __align__(16) __nv_bfloat16 g_Wcc_h[(size_t)CE * 512],  g_Wcc_l[(size_t)CE * 512];
__device__ __align__(16) __nv_bfloat16 g_Wgwcs_h[(size_t)1024 * 1024], g_Wgwcs_l[(size_t)1024 * 1024];
__device__ __align__(16) __nv_bfloat16 g_Wcwcs_h[(size_t)1024 * 512],  g_Wcwcs_l[(size_t)1024 * 512];
__device__ __align__(16) __nv_bfloat16 g_Wgwwe_h[(size_t)WE * 1024], g_Wgwwe_l[(size_t)WE * 1024];
__device__ __align__(16) __nv_bfloat16 g_Wcwwe_h[(size_t)WE * 512],  g_Wcwwe_l[(size_t)WE * 512];
__device__ __align__(16) __nv_bfloat16 g_Wghc_h[(size_t)H * 1024], g_Wghc_l[(size_t)H * 1024];
__device__ __align__(16) __nv_bfloat16 g_Wchc_h[(size_t)H * 512],  g_Wchc_l[(size_t)H * 512];
__device__ __align__(16) __nv_bfloat16 g_Wghw_h[(size_t)H * 1024], g_Wghw_l[(size_t)H * 1024];
__device__ __align__(16) __nv_bfloat16 g_Wchw_h[(size_t)H * 512],  g_Wchw_l[(size_t)H * 512];

// ---------------- helpers ----------------------------------------------------
__device__ __forceinline__ uint32_t smem_u32(const void* p) {
    uint32_t a;
    asm("{ .reg .u64 t; cvta.to.shared.u64 t, %1; cvt.u32.u64 %0, t; }" : "=r"(a) : "l"(p));
    return a;
}
__device__ __forceinline__ void split2(float v, __nv_bfloat16& h, __nv_bfloat16& l) {
    h = __float2bfloat16(v);
    l = __float2bfloat16(v - __bfloat162float(h));
}
__device__ __forceinline__ unsigned pack_bf(__nv_bfloat16 a, __nv_bfloat16 b) {
    unsigned short x = *(unsigned short*)&a, y = *(unsigned short*)&b;
    return (unsigned)x | ((unsigned)y << 16);
}
__device__ __forceinline__ size_t tiled_off(int row, int col, int NKt) {
    return ((size_t)((row >> 7) * NKt + (col >> 5)) * 128 + (row & 127)) * 32 + (col & 31);
}
__device__ __forceinline__ void ldm4(uint32_t r[4], uint32_t saddr) {
    asm volatile("ldmatrix.sync.aligned.m8n8.x4.shared.b16 {%0,%1,%2,%3}, [%4];"
                 : "=r"(r[0]), "=r"(r[1]), "=r"(r[2]), "=r"(r[3]) : "r"(saddr));
}
__device__ __forceinline__ void mma16816(float c[4], const uint32_t a[4], const uint32_t b[2]) {
    asm volatile(
        "mma.sync.aligned.m16n8k16.row.col.f32.bf16.bf16.f32 "
        "{%0,%1,%2,%3},{%4,%5,%6,%7},{%8,%9},{%0,%1,%2,%3};"
        : "+f"(c[0]), "+f"(c[1]), "+f"(c[2]), "+f"(c[3])
        : "r"(a[0]), "r"(a[1]), "r"(a[2]), "r"(a[3]), "r"(b[0]), "r"(b[1]));
}

// packed f32x2 (FFMA2) helpers for the scalar path
__device__ __forceinline__ unsigned long long pk2(float x) {
    unsigned long long d;
    unsigned u = __float_as_uint(x);
    asm("mov.b64 %0, {%1, %1};" : "=l"(d) : "r"(u));
    return d;
}
__device__ __forceinline__ void ffma2(unsigned long long& d,
                                      unsigned long long a,
                                      unsigned long long b) {
    asm("fma.rn.f32x2 %0, %1, %2, %0;" : "+l"(d) : "l"(a), "l"(b));
}
__device__ __forceinline__ float pick2(unsigned long long v, int half) {
    return __uint_as_float(half ? (unsigned)(v >> 32) : (unsigned)v);
}

// group barrier: n CTAs of one dependence group rendezvous on bar[idx]
__device__ __forceinline__ void grid_bar(int* bar, int idx, int n) {
    __syncthreads();
    if (threadIdx.x == 0) {
        __threadfence();
        atomicAdd(&bar[idx], 1);
        while (((volatile int*)bar)[idx] < n) __nanosleep(32);
        __threadfence();
    }
    __syncthreads();
}

// =============== split-bf16 mma.sync core: 128x128 tile, 256 thr ============
// Term-major MMA issue: all AhBh, then AhBl, then AlBh. Same per-accumulator
// order as term-minor (bit-exact), but same-acc reuse distance = 16 tiles,
// hiding HMMA latency under in-order issue.
template<bool CG>
__device__ __forceinline__ void mma_core(
    const __nv_bfloat16* __restrict__ Ah, const __nv_bfloat16* __restrict__ Al,
    const __nv_bfloat16* __restrict__ Bh, const __nv_bfloat16* __restrict__ Bl,
    int NKt, int mt, int nt, float acc[4][4][4])
{
    __shared__ __align__(16) __nv_bfloat16 sA[2][128][40];
    __shared__ __align__(16) __nv_bfloat16 sB[2][128][40];
    const int tid = threadIdx.x, lane = tid & 31, warp = tid >> 5;
    const int wy = warp >> 2, wx = warp & 3;
    const int gq = lane >> 3, rr = lane & 7;
    uint4 pA[2][2], pB[2][2];

    auto gload = [&](int c) {
        #pragma unroll
        for (int i = 0; i < 2; i++) {
            int idx = tid + i * 256;
            int r = idx >> 2, c8 = idx & 3;
            size_t ta = ((size_t)(mt * NKt + c) * 128 + r) * 32 + c8 * 8;
            size_t tb = ((size_t)(nt * NKt + c) * 128 + r) * 32 + c8 * 8;
            if (CG) {
                pA[0][i] = __ldcg((const uint4*)(Ah + ta));
                pA[1][i] = __ldcg((const uint4*)(Al + ta));
            } else {
                pA[0][i] = *(const uint4*)(Ah + ta);
                pA[1][i] = *(const uint4*)(Al + ta);
            }
            pB[0][i] = *(const uint4*)(Bh + tb);
            pB[1][i] = *(const uint4*)(Bl + tb);
        }
    };
    auto sstore = [&]() {
        #pragma unroll
        for (int i = 0; i < 2; i++) {
            int idx = tid + i * 256;
            int r = idx >> 2, c8 = idx & 3;
            *(uint4*)&sA[0][r][c8 * 8] = pA[0][i];
            *(uint4*)&sA[1][r][c8 * 8] = pA[1][i];
            *(uint4*)&sB[0][r][c8 * 8] = pB[0][i];
            *(uint4*)&sB[1][r][c8 * 8] = pB[1][i];
        }
    };
    const uint32_t bAh = smem_u32(&sA[0][0][0]), bAl = smem_u32(&sA[1][0][0]);
    const uint32_t bBh = smem_u32(&sB[0][0][0]), bBl = smem_u32(&sB[1][0][0]);

    gload(0);
    for (int c = 0;;) {
        sstore();
        __syncthreads();
        int cn = c + 1;
        if (cn < NKt) gload(cn);
        #pragma unroll
        for (int s = 0; s < 2; s++) {
            uint32_t ah[4][4], al[4][4], bh[4][2], bl[4][2];
            #pragma unroll
            for (int mi = 0; mi < 4; mi++) {
                int row = wy * 64 + mi * 16 + (gq & 1) * 8 + rr;
                int col = s * 16 + (gq >> 1) * 8;
                uint32_t off = (uint32_t)(row * 40 + col) * 2;
                ldm4(ah[mi], bAh + off);
                ldm4(al[mi], bAl + off);
            }
            #pragma unroll
            for (int nb = 0; nb < 2; nb++) {
                int nrow = wx * 32 + nb * 16 + (gq >> 1) * 8 + rr;
                int col = s * 16 + (gq & 1) * 8;
                uint32_t off = (uint32_t)(nrow * 40 + col) * 2;
                uint32_t t0[4], t1[4];
                ldm4(t0, bBh + off);
                ldm4(t1, bBl + off);
                bh[nb * 2][0] = t0[0]; bh[nb * 2][1] = t0[1];
                bh[nb * 2 + 1][0] = t0[2]; bh[nb * 2 + 1][1] = t0[3];
                bl[nb * 2][0] = t1[0]; bl[nb * 2][1] = t1[1];
                bl[nb * 2 + 1][0] = t1[2]; bl[nb * 2 + 1][1] = t1[3];
            }
            // term-major: 16 independent accumulators between same-acc MMAs
            #pragma unroll
            for (int mi = 0; mi < 4; mi++)
                #pragma unroll
                for (int ni = 0; ni < 4; ni++)
                    mma16816(acc[mi][ni], ah[mi], bh[ni]);
            #pragma unroll
            for (int mi = 0; mi < 4; mi++)
                #pragma unroll
                for (int ni = 0; ni < 4; ni++)
                    mma16816(acc[mi][ni], ah[mi], bl[ni]);
            #pragma unroll
            for (int mi = 0; mi < 4; mi++)
                #pragma unroll
                for (int ni = 0; ni < 4; ni++)
                    mma16816(acc[mi][ni], al[mi], bh[ni]);
        }
        __syncthreads();
        c = cn;
        if (c >= NKt) break;
    }
}

// =============== split-bf16 mma.sync core: 64x64 tile, 128 thr, CG A-loads ==
__device__ __forceinline__ void mma_core64cg(
    const __nv_bfloat16* __restrict__ Ah, const __nv_bfloat16* __restrict__ Al,
    const __nv_bfloat16* __restrict__ Bh, const __nv_bfloat16* __restrict__ Bl,
    int NKt, int bm, int bn, float acc[4][2][4])
{
    __shared__ __align__(16) __nv_bfloat16 sA[2][64][40];
    __shared__ __align__(16) __nv_bfloat16 sB[2][64][40];
    const int tid = threadIdx.x, lane = tid & 31, wx = tid >> 5;
    const int gq = lane >> 3, rr = lane & 7;
    uint4 pA[2][2], pB[2][2];
    const int mtb = bm >> 7, mro = bm & 127;
    const int ntb = bn >> 7, nro = bn & 127;

    auto gload = [&](int c) {
        #pragma unroll
        for (int i = 0; i < 2; i++) {
            int idx = tid + i * 128;
            int r = idx >> 2, c8 = idx & 3;
            size_t ta = ((size_t)(mtb * NKt + c) * 128 + mro + r) * 32 + c8 * 8;
            size_t tb = ((size_t)(ntb * NKt + c) * 128 + nro + r) * 32 + c8 * 8;
            pA[0][i] = __ldcg((const uint4*)(Ah + ta));
            pA[1][i] = __ldcg((const uint4*)(Al + ta));
            pB[0][i] = *(const uint4*)(Bh + tb);
            pB[1][i] = *(const uint4*)(Bl + tb);
        }
    };
    auto sstore = [&]() {
        #pragma unroll
        for (int i = 0; i < 2; i++) {
            int idx = tid + i * 128;
            int r = idx >> 2, c8 = idx & 3;
            *(uint4*)&sA[0][r][c8 * 8] = pA[0][i];
            *(uint4*)&sA[1][r][c8 * 8] = pA[1][i];
            *(uint4*)&sB[0][r][c8 * 8] = pB[0][i];
            *(uint4*)&sB[1][r][c8 * 8] = pB[1][i];
        }
    };
    const uint32_t bAh = smem_u32(&sA[0][0][0]), bAl = smem_u32(&sA[1][0][0]);
    const uint32_t bBh = smem_u32(&sB[0][0][0]), bBl = smem_u32(&sB[1][0][0]);

    gload(0);
    for (int c = 0;;) {
        sstore();
        __syncthreads();
        int cn = c + 1;
        if (cn < NKt) gload(cn);
        #pragma unroll
        for (int s = 0; s < 2; s++) {
            uint32_t ah[4][4], al[4][4], bh[2][2], bl[2][2];
            #pragma unroll
            for (int mi = 0; mi < 4; mi++) {
                int row = mi * 16 + (gq & 1) * 8 + rr;
                int col = s * 16 + (gq >> 1) * 8;
                uint32_t off = (uint32_t)(row * 40 + col) * 2;
                ldm4(ah[mi], bAh + off);
                ldm4(al[mi], bAl + off);
            }
            {
                int nrow = wx * 16 + (gq >> 1) * 8 + rr;
                int col = s * 16 + (gq & 1) * 8;
                uint32_t off = (uint32_t)(nrow * 40 + col) * 2;
                uint32_t t0[4], t1[4];
                ldm4(t0, bBh + off);
                ldm4(t1, bBl + off);
                bh[0][0] = t0[0]; bh[0][1] = t0[1];
                bh[1][0] = t0[2]; bh[1][1] = t0[3];
                bl[0][0] = t1[0]; bl[0][1] = t1[1];
                bl[1][0] = t1[2]; bl[1][1] = t1[3];
            }
            // term-major: 8 independent accumulators between same-acc MMAs
            #pragma unroll
            for (int mi = 0; mi < 4; mi++)
                #pragma unroll
                for (int ni = 0; ni < 2; ni++)
                    mma16816(acc[mi][ni], ah[mi], bh[ni]);
            #pragma unroll
            for (int mi = 0; mi < 4; mi++)
                #pragma unroll
                for (int ni = 0; ni < 2; ni++)
                    mma16816(acc[mi][ni], ah[mi], bl[ni]);
            #pragma unroll
            for (int mi = 0; mi < 4; mi++)
                #pragma unroll
                for (int ni = 0; ni < 2; ni++)
                    mma16816(acc[mi][ni], al[mi], bh[ni]);
        }
        __syncthreads();
        c = cn;
        if (c >= NKt) break;
    }
}

// ---- GEMM + bias: C[M,Nd] fp32 = A@W + bias (ACC: C += A@W, no bias) ----
template<bool ACC>
__global__ void __launch_bounds__(256)
k_mm_bias_t(const __nv_bfloat16* __restrict__ Ah, const __nv_bfloat16* __restrict__ Al,
            const __nv_bfloat16* __restrict__ Bh, const __nv_bfloat16* __restrict__ Bl,
            const float* __restrict__ bias, float* __restrict__ C, int Nd, int NKt)
{
    float acc[4][4][4] = {};
    int nt = blockIdx.x, mt = blockIdx.y;
    mma_core<false>(Ah, Al, Bh, Bl, NKt, mt, nt, acc);
    int lane = threadIdx.x & 31, warp = threadIdx.x >> 5;
    int wy = warp >> 2, wx = warp & 3;
    int bm = mt * 128, bn = nt * 128;
    #pragma unroll
    for (int mi = 0; mi < 4; mi++) {
        #pragma unroll
        for (int ni = 0; ni < 4; ni++) {
            int n0 = bn + wx * 32 + ni * 8 + (lane & 3) * 2;
            int r0 = bm + wy * 64 + mi * 16 + (lane >> 2);
            float* p0 = C + (size_t)r0 * Nd + n0;
            float* p1 = C + (size_t)(r0 + 8) * Nd + n0;
            float2 v0, v1;
            if (ACC) {
                float2 o0 = *(float2*)p0, o1 = *(float2*)p1;
                v0 = {acc[mi][ni][0] + o0.x, acc[mi][ni][1] + o0.y};
                v1 = {acc[mi][ni][2] + o1.x, acc[mi][ni][3] + o1.y};
            } else {
                v0 = {acc[mi][ni][0] + bias[n0], acc[mi][ni][1] + bias[n0 + 1]};
                v1 = {acc[mi][ni][2] + bias[n0], acc[mi][ni][3] + bias[n0 + 1]};
            }
            *(float2*)p0 = v0;
            *(float2*)p1 = v1;
        }
    }
}

// ==================== PERSISTENT char bi-GRU (all 16 steps) =================
// X-projections come from tiny per-character tables Eg[256,1024], Ec[256,512]
// (L2-resident), indexed through charseqs — exact gather∘linear factorization.
__global__ void __launch_bounds__(256)
k_char_rnn(const __nv_bfloat16* __restrict__ Wgh_h, const __nv_bfloat16* __restrict__ Wgh_l,
           const __nv_bfloat16* __restrict__ Wch_h, const __nv_bfloat16* __restrict__ Wch_l,
           const float* __restrict__ Eg, const float* __restrict__ Ec,
           const int* __restrict__ charseqs, const int* __restrict__ lens,
           float* __restrict__ Hfp, float* __restrict__ Ug,
           __nv_bfloat16* __restrict__ Hh, __nv_bfloat16* __restrict__ Hl,
           __nv_bfloat16* __restrict__ RHh, __nv_bfloat16* __restrict__ RHl,
           int* __restrict__ bar)
{
    const int lane = threadIdx.x & 31, warp = threadIdx.x >> 5;
    const int wy = warp >> 2, wx = warp & 3;
    const int Nseq = U_, T = TC;
    const int mt = blockIdx.x >> 2;
    const int sub = blockIdx.x & 3;
    const int bm = mt * 128;

    #pragma unroll 1
    for (int t = 0; t < TC; t++) {
        // ---------- gates: 2 n-tiles per CTA, same mt ----------
        #pragma unroll 1
        for (int rep = 0; rep < 2; rep++) {
            int nt = sub * 2 + rep;
            float acc[4][4][4] = {};
            mma_core<true>(Hh, Hl, Wgh_h, Wgh_l, H / 32, mt, nt, acc);
            int bn = nt * 128;
            bool isR = (bn + 128 <= H);
            #pragma unroll
            for (int mi = 0; mi < 4; mi++) {
                #pragma unroll
                for (int hh = 0; hh < 2; hh++) {
                    int r = bm + wy * 64 + mi * 16 + (lane >> 2) + hh * 8;
                    int dir = (r >= Nseq);
                    int n = dir ? r - Nseq : r;
                    int len = lens[n];
                    int te = dir ? max(0, min(len - 1 - t, T - 1)) : t;
                    int id = charseqs[n * T + te];
                    const float* xg = Eg + (size_t)id * (2 * H);
                    #pragma unroll
                    for (int ni = 0; ni < 4; ni++) {
                        int c0 = bn + wx * 32 + ni * 8 + (lane & 3) * 2;
                        float a0 = acc[mi][ni][hh * 2 + 0];
                        float a1 = acc[mi][ni][hh * 2 + 1];
                        float g0 = 1.f / (1.f + __expf(-(xg[c0] + a0)));
                        float g1 = 1.f / (1.f + __expf(-(xg[c0 + 1] + a1)));
                        if (isR) {
                            float2 hv = __ldcg((const float2*)(Hfp + (size_t)r * H + c0));
                            float rh0 = g0 * hv.x, rh1 = g1 * hv.y;
                            __nv_bfloat16 h0, l0, h1, l1;
                            split2(rh0, h0, l0);
                            split2(rh1, h1, l1);
                            size_t o = tiled_off(r, c0, H / 32);
                            __stcg((unsigned*)(RHh + o), pack_bf(h0, h1));
                            __stcg((unsigned*)(RHl + o), pack_bf(l0, l1));
                        } else {
                            float2 uv = {g0, g1};
                            __stcg((float2*)(Ug + (size_t)r * H + (c0 - H)), uv);
                        }
                    }
                }
            }
        }
        grid_bar(bar, 2 * t * 32 + mt, 4);

        // ---------- cand: 1 n-tile per CTA, same mt ----------
        {
            int nt = sub;
            float acc[4][4][4] = {};
            mma_core<true>(RHh, RHl, Wch_h, Wch_l, H / 32, mt, nt, acc);
            int bn = nt * 128;
            #pragma unroll
            for (int mi = 0; mi < 4; mi++) {
                #pragma unroll
                for (int hh = 0; hh < 2; hh++) {
                    int r = bm + wy * 64 + mi * 16 + (lane >> 2) + hh * 8;
                    int dir = (r >= Nseq);
                    int n = dir ? r - Nseq : r;
                    int len = lens[n];
                    if (t >= len) continue;   // frozen
                    int te = dir ? max(0, min(len - 1 - t, T - 1)) : t;
                    int id = charseqs[n * T + te];
                    const float* xc = Ec + (size_t)id * H;
                    #pragma unroll
                    for (int ni = 0; ni < 4; ni++) {
                        int c0 = bn + wx * 32 + ni * 8 + (lane & 3) * 2;
                        float cc0 = tanhf(xc[c0] + acc[mi][ni][hh * 2 + 0]);
                        float cc1 = tanhf(xc[c0 + 1] + acc[mi][ni][hh * 2 + 1]);
                        float2 hv = __ldcg((const float2*)(Hfp + (size_t)r * H + c0));
                        float2 uv = __ldcg((const float2*)(Ug + (size_t)r * H + c0));
                        float hn0 = uv.x * hv.x + (1.f - uv.x) * cc0;
                        float hn1 = uv.y * hv.y + (1.f - uv.y) * cc1;
                        float2 hw = {hn0, hn1};
                        __stcg((float2*)(Hfp + (size_t)r * H + c0), hw);
                        __nv_bfloat16 h0, l0, h1, l1;
                        split2(hn0, h0, l0);
                        split2(hn1, h1, l1);
                        size_t o = tiled_off(r, c0, H / 32);
                        __stcg((unsigned*)(Hh + o), pack_bf(h0, h1));
                        __stcg((unsigned*)(Hl + o), pack_bf(l0, l1));
                    }
                }
            }
        }
        grid_bar(bar, (2 * t + 1) * 32 + mt, 4);
    }
}

// ==================== PERSISTENT word bi-GRU (all 64 steps) =================
__global__ void __launch_bounds__(128)
k_word_rnn(const __nv_bfloat16* __restrict__ Wgh_h, const __nv_bfloat16* __restrict__ Wgh_l,
           const __nv_bfloat16* __restrict__ Wch_h, const __nv_bfloat16* __restrict__ Wch_l,
           const float* __restrict__ Xg, const float* __restrict__ Xc,
           const int* __restrict__ lens,
           float* __restrict__ Hfp, float* __restrict__ Ug,
           __nv_bfloat16* __restrict__ Hh, __nv_bfloat16* __restrict__ Hl,
           __nv_bfloat16* __restrict__ RHh, __nv_bfloat16* __restrict__ RHl,
           int* __restrict__ bar)
{
    const int cta = blockIdx.x;
    const int mtile = cta >> 4, ntile = cta & 15;
    const int bm = mtile * 64;
    const int lane = threadIdx.x & 31, wx = threadIdx.x >> 5;
    const int Nseq = B_, T = TW;

    #pragma unroll 1
    for (int t = 0; t < TW; t++) {
        // ---------- gates ----------
        {
            float acc[4][2][4] = {};
            int bn = ntile * 64;
            mma_core64cg(Hh, Hl, Wgh_h, Wgh_l, H / 32, bm, bn, acc);
            bool isR = (bn + 64 <= H);
            #pragma unroll
            for (int mi = 0; mi < 4; mi++) {
                #pragma unroll
                for (int hh = 0; hh < 2; hh++) {
                    int r = bm + mi * 16 + (lane >> 2) + hh * 8;
                    int dir = (r >= Nseq);
                    int n = dir ? r - Nseq : r;
                    int len = lens[n];
                    int te = dir ? max(0, min(len - 1 - t, T - 1)) : t;
                    const float* xg = Xg + ((size_t)n * T + te) * (2 * H);
                    #pragma unroll
                    for (int ni = 0; ni < 2; ni++) {
                        int c0 = bn + wx * 16 + ni * 8 + (lane & 3) * 2;
                        float a0 = acc[mi][ni][hh * 2 + 0];
                        float a1 = acc[mi][ni][hh * 2 + 1];
                        float g0 = 1.f / (1.f + __expf(-(xg[c0] + a0)));
                        float g1 = 1.f / (1.f + __expf(-(xg[c0 + 1] + a1)));
                        if (isR) {
                            float2 hv = __ldcg((const float2*)(Hfp + (size_t)r * H + c0));
                            float rh0 = g0 * hv.x, rh1 = g1 * hv.y;
                            __nv_bfloat16 h0, l0, h1, l1;
                            split2(rh0, h0, l0);
                            split2(rh1, h1, l1);
                            size_t o = tiled_off(r, c0, H / 32);
                            __stcg((unsigned*)(RHh + o), pack_bf(h0, h1));
                            __stcg((unsigned*)(RHl + o), pack_bf(l0, l1));
                        } else {
                            float2 uv = {g0, g1};
                            __stcg((float2*)(Ug + (size_t)r * H + (c0 - H)), uv);
                        }
                    }
                }
            }
        }
        grid_bar(bar, 2 * t * 8 + mtile, 16);

        // ---------- cand ----------
        if (ntile < 8) {
            float acc[4][2][4] = {};
            int bn = ntile * 64;
            mma_core64cg(RHh, RHl, Wch_h, Wch_l, H / 32, bm, bn, acc);
            #pragma unroll
            for (int mi = 0; mi < 4; mi++) {
                #pragma unroll
                for (int hh = 0; hh < 2; hh++) {
                    int r = bm + mi * 16 + (lane >> 2) + hh * 8;
                    int dir = (r >= Nseq);
                    int n = dir ? r - Nseq : r;
                    int len = lens[n];
                    if (t >= len) continue;   // frozen
                    int te = dir ? max(0, min(len - 1 - t, T - 1)) : t;
                    const float* xc = Xc + ((size_t)n * T + te) * H;
                    #pragma unroll
                    for (int ni = 0; ni < 2; ni++) {
                        int c0 = bn + wx * 16 + ni * 8 + (lane & 3) * 2;
                        float cc0 = tanhf(xc[c0] + acc[mi][ni][hh * 2 + 0]);
                        float cc1 = tanhf(xc[c0 + 1] + acc[mi][ni][hh * 2 + 1]);
                        float2 hv = __ldcg((const float2*)(Hfp + (size_t)r * H + c0));
                        float2 uv = __ldcg((const float2*)(Ug + (size_t)r * H + c0));
                        float hn0 = uv.x * hv.x + (1.f - uv.x) * cc0;
                        float hn1 = uv.y * hv.y + (1.f - uv.y) * cc1;
                        float2 hw = {hn0, hn1};
                        __stcg((float2*)(Hfp + (size_t)r * H + c0), hw);
                        __nv_bfloat16 h0, l0, h1, l1;
                        split2(hn0, h0, l0);
                        split2(hn1, h1, l1);
                        size_t o = tiled_off(r, c0, H / 32);
                        __stcg((unsigned*)(Hh + o), pack_bf(h0, h1));
                        __stcg((unsigned*)(Hl + o), pack_bf(l0, l1));
                    }
                }
            }
        }
        grid_bar(bar, (2 * t + 1) * 8 + mtile, 16);
    }
}

// ---- fused one-time weight split (all 10 segments in one launch) ----
__device__ __forceinline__ void prep1(const float* W, int idx, int Nd, int NKt,
                                      __nv_bfloat16* Bh, __nv_bfloat16* Bl) {
    int k = idx / Nd, n = idx % Nd;
    __nv_bfloat16 h, l;
    split2(W[idx], h, l);
    size_t off = ((size_t)((n >> 7) * NKt + (k >> 5)) * 128 + (n & 127)) * 32 + (k & 31);
    Bh[off] = h; Bl[off] = l;
}

#define Q1 (CE * 1024)
#define Q2 (Q1 + CE * 512)
#define Q3 (Q2 + 1024 * 1024)
#define Q4 (Q3 + 1024 * 512)
#define Q5 (Q4 + WE * 1024)
#define Q6 (Q5 + WE * 512)
#define Q7 (Q6 + H * 1024)
#define Q8 (Q7 + H * 512)
#define Q9 (Q8 + H * 1024)
#define Q10 (Q9 + H * 512)

__global__ void k_prep_all(const float* __restrict__ Wg_c, const float* __restrict__ Wc_c,
                           const float* __restrict__ Wg_w, const float* __restrict__ Wc_w,
                           __nv_bfloat16* Wgc_h, __nv_bfloat16* Wgc_l,
                           __nv_bfloat16* Wcc_h, __nv_bfloat16* Wcc_l,
                           __nv_bfloat16* Wgwcs_h, __nv_bfloat16* Wgwcs_l,
                           __nv_bfloat16* Wcwcs_h, __nv_bfloat16* Wcwcs_l,
                           __nv_bfloat16* Wgwwe_h, __nv_bfloat16* Wgwwe_l,
                           __nv_bfloat16* Wcwwe_h, __nv_bfloat16* Wcwwe_l,
                           __nv_bfloat16* Wghc_h, __nv_bfloat16* Wghc_l,
                           __nv_bfloat16* Wchc_h, __nv_bfloat16* Wchc_l,
                           __nv_bfloat16* Wghw_h, __nv_bfloat16* Wghw_l,
                           __nv_bfloat16* Wchw_h, __nv_bfloat16* Wchw_l) {
    int i = blockIdx.x * blockDim.x + threadIdx.x;
    if (i < Q1)      prep1(Wg_c, i, 1024, CE / 32, Wgc_h, Wgc_l);
    else if (i < Q2) prep1(Wc_c, i - Q1, 512, CE / 32, Wcc_h, Wcc_l);
    else if (i < Q3) prep1(Wg_w, i - Q2, 1024, 1024 / 32, Wgwcs_h, Wgwcs_l);
    else if (i < Q4) prep1(Wc_w, i - Q3, 512, 1024 / 32, Wcwcs_h, Wcwcs_l);
    else if (i < Q5) prep1(Wg_w + (size_t)1024 * 1024, i - Q4, 1024, WE / 32, Wgwwe_h, Wgwwe_l);
    else if (i < Q6) prep1(Wc_w + (size_t)1024 * 512, i - Q5, 512, WE / 32, Wcwwe_h, Wcwwe_l);
    else if (i < Q7) prep1(Wg_c + (size_t)CE * 1024, i - Q6, 1024, H / 32, Wghc_h, Wghc_l);
    else if (i < Q8) prep1(Wc_c + (size_t)CE * 512, i - Q7, 512, H / 32, Wchc_h, Wchc_l);
    else if (i < Q9) prep1(Wg_w + (size_t)WD * 1024, i - Q8, 1024, H / 32, Wghw_h, Wghw_l);
    else if (i < Q10) prep1(Wc_w + (size_t)WD * 512, i - Q9, 512, H / 32, Wchw_h, Wchw_l);
}

// ---- split char_emb [NC x CE] into tiled image ------------------------------
__global__ void k_split_ce(const float* __restrict__ ce,
                           __nv_bfloat16* __restrict__ Ah,
                           __nv_bfloat16* __restrict__ Al) {
    int i = blockIdx.x * blockDim.x + threadIdx.x;
    if (i >= NC * CE) return;
    int r = i >> 7, c = i & (CE - 1);
    __nv_bfloat16 h, l;
    split2(ce[i], h, l);
    size_t off = tiled_off(r, c, CE / 32);
    Ah[off] = h; Al[off] = l;
}

// build unique-word concat-state split image [U x 2H] from final Hc
__global__ void k_build_u(const float* __restrict__ Hc,
                          __nv_bfloat16* __restrict__ Ah,
                          __nv_bfloat16* __restrict__ Al) {
    int i = blockIdx.x * blockDim.x + threadIdx.x;
    if (i >= U_ * 2 * H) return;
    int c = i & (2 * H - 1);
    int u = i >> 10;
    float v = (c < H) ? Hc[(size_t)u * H + c] : Hc[(size_t)(U_ + u) * H + (c - H)];
    __nv_bfloat16 h, l;
    split2(v, h, l);
    size_t off = tiled_off(u, c, (2 * H) / 32);
    Ah[off] = h; Al[off] = l;
}

// gather word embeddings only (WE cols) into split image [B*TW x WE]
__global__ void k_gather_we(const int* __restrict__ wids,
                            const float* __restrict__ word_emb,
                            __nv_bfloat16* __restrict__ Ah,
                            __nv_bfloat16* __restrict__ Al) {
    int i = blockIdx.x * blockDim.x + threadIdx.x;
    if (i >= B_ * TW * WE) return;
    int c = i & (WE - 1);
    int bt = i >> 8;
    float v = word_emb[(size_t)wids[bt] * WE + c];
    __nv_bfloat16 h, l;
    split2(v, h, l);
    size_t off = tiled_off(bt, c, WE / 32);
    Ah[off] = h; Al[off] = l;
}

// scatter unique projections to per-token X buffers (bias already in P)
__global__ void k_combine(const int* __restrict__ cids,
                          const float* __restrict__ Pg, const float* __restrict__ Pc,
                          float* __restrict__ Xg, float* __restrict__ Xc) {
    int i = blockIdx.x * blockDim.x + threadIdx.x;
    const int total = B_ * TW * 384;
    if (i >= total) return;
    int bt = i / 384, j = i % 384;
    int u = cids[bt];
    if (j < 256)
        ((float4*)Xg)[(size_t)bt * 256 + j] = ((const float4*)Pg)[(size_t)u * 256 + j];
    else
        ((float4*)Xc)[(size_t)bt * 128 + (j - 256)] = ((const float4*)Pc)[(size_t)u * 128 + (j - 256)];
}

// ============ small 64x64 / 4x4 FFMA2 core (head) ===========================
__device__ __forceinline__ void gemm64_2(const float* __restrict__ A,
                                         const float* __restrict__ Bm,
                                         int K, int N, int bm, int bn,
                                         unsigned long long acc[4][2]) {
    __shared__ float As[2][16][64];
    __shared__ float Bs[2][16][64];
    const int tid = threadIdx.x;
    const int tx = tid & 15;
    const int ty = tid >> 4;
    float4 aR, bR;
    auto loadA = [&](int k0) {
        int r = tid >> 2, c4 = tid & 3;
        aR = *(const float4*)(A + (size_t)(bm + r) * K + k0 + c4 * 4);
    };
    auto loadB = [&](int k0) {
        int kr = tid >> 4, c4 = tid & 15;
        bR = *(const float4*)(Bm + (size_t)(k0 + kr) * N + bn + c4 * 4);
    };
    auto stage = [&](int buf) {
        int r = tid >> 2, c4 = tid & 3;
        As[buf][c4 * 4 + 0][r] = aR.x;
        As[buf][c4 * 4 + 1][r] = aR.y;
        As[buf][c4 * 4 + 2][r] = aR.z;
        As[buf][c4 * 4 + 3][r] = aR.w;
        int kr = tid >> 4, cb = tid & 15;
        *(float4*)&Bs[buf][kr][cb * 4] = bR;
    };
    loadA(0); loadB(0);
    stage(0);
    __syncthreads();
    int buf = 0;
    for (int k0 = 0;;) {
        int kn = k0 + 16;
        if (kn < K) { loadA(kn); loadB(kn); }
        #pragma unroll
        for (int k = 0; k < 16; k++) {
            float4 a = *(const float4*)&As[buf][k][ty * 4];
            ulonglong2 bp = *(const ulonglong2*)&Bs[buf][k][tx * 4];
            float av[4] = {a.x, a.y, a.z, a.w};
            #pragma unroll
            for (int i = 0; i < 4; i++) {
                unsigned long long ad = pk2(av[i]);
                ffma2(acc[i][0], ad, bp.x);
                ffma2(acc[i][1], ad, bp.y);
            }
        }
        if (kn >= K) break;
        stage(buf ^ 1);
        __syncthreads();
        buf ^= 1;
        k0 = kn;
    }
}

__global__ __launch_bounds__(256)
void k_sgemm_bias_s(const float* __restrict__ A, const float* __restrict__ Bm,
                    const float* __restrict__ bias, float* __restrict__ C,
                    int N, int K, int act) {
    unsigned long long acc[4][2] = {};
    int bm = blockIdx.y * 64, bn = blockIdx.x * 64;
    gemm64_2(A, Bm, K, N, bm, bn, acc);
    const int tx = threadIdx.x & 15, ty = threadIdx.x >> 4;
    #pragma unroll
    for (int i = 0; i < 4; i++) {
        int r = bm + ty * 4 + i;
        #pragma unroll
        for (int q = 0; q < 4; q++) {
            int c = bn + tx * 4 + q;
            float v = pick2(acc[i][q >> 1], q & 1) + bias[c];
            if (act) v = v > 0.f ? v : 0.2f * v;
            C[(size_t)r * N + c] = v;
        }
    }
}

// ---------------- misc small kernels -----------------------------------------
__global__ void k_copy_states(const float* __restrict__ Hw, float* __restrict__ out) {
    int i = blockIdx.x * blockDim.x + threadIdx.x;
    if (i >= B_ * 2 * H) return;
    int c = i % (2 * H);
    int b = i / (2 * H);
    out[i] = (c < H) ? Hw[(size_t)b * H + c] : Hw[(size_t)(B_ + b) * H + (c - H)];
}

__global__ void k_fc2(const float* __restrict__ hidden, const float* __restrict__ W2,
                      const float* __restrict__ b2, float* __restrict__ out) {
    int i = blockIdx.x * blockDim.x + threadIdx.x;
    if (i >= B_ * 2) return;
    int b = i >> 1, j = i & 1;
    float s = b2[j];
    #pragma unroll
    for (int k = 0; k < 64; k++) s = fmaf(hidden[b * 64 + k], W2[k * 2 + j], s);
    out[i] = s;
}

// ---------------- host orchestration ----------------------------------------
extern "C" void kernel_launch(void* const* d_in, const int* in_sizes, int n_in,
                              void* d_out, int out_size) {
    const int*   charseqs      = (const int*)d_in[0];
    const int*   charseq_lens  = (const int*)d_in[1];
    const int*   charseq_ids   = (const int*)d_in[2];
    const int*   word_ids      = (const int*)d_in[3];
    const int*   sentence_lens = (const int*)d_in[4];
    const float* char_emb      = (const float*)d_in[5];
    const float* word_emb      = (const float*)d_in[6];
    const float* Wg_c = (const float*)d_in[7];
    const float* bg_c = (const float*)d_in[8];
    const float* Wc_c = (const float*)d_in[9];
    const float* bc_c = (const float*)d_in[10];
    const float* Wg_w = (const float*)d_in[11];
    const float* bg_w = (const float*)d_in[12];
    const float* Wc_w = (const float*)d_in[13];
    const float* bc_w = (const float*)d_in[14];
    const float* W1   = (const float*)d_in[15];
    const float* b1   = (const float*)d_in[16];
    const float* W2   = (const float*)d_in[17];
    const float* b2   = (const float*)d_in[18];
    float* out = (float*)d_out;

    float *Eg, *Ec, *Hc, *Uc, *Xg_w, *Xc_w, *Hw, *Uw, *Pg, *Pc, *states, *hidden;
    int* bar;
    __nv_bfloat16 *ceh, *cel, *uAh, *uAl, *weAh, *weAl, *Hch, *Hcl, *RHh, *RHl;
    __nv_bfloat16 *Hwh, *Hwl, *RHwh, *RHwl;
    __nv_bfloat16 *Wgc_h, *Wgc_l, *Wcc_h, *Wcc_l;
    __nv_bfloat16 *Wgwcs_h, *Wgwcs_l, *Wcwcs_h, *Wcwcs_l;
    __nv_bfloat16 *Wgwwe_h, *Wgwwe_l, *Wcwwe_h, *Wcwwe_l;
    __nv_bfloat16 *Wghc_h, *Wghc_l, *Wchc_h, *Wchc_l, *Wghw_h, *Wghw_l, *Wchw_h, *Wchw_l;
    cudaGetSymbolAddress((void**)&Eg,     g_Eg);
    cudaGetSymbolAddress((void**)&Ec,     g_Ec);
    cudaGetSymbolAddress((void**)&Hc,     g_Hc);
    cudaGetSymbolAddress((void**)&Uc,     g_Uc);
    cudaGetSymbolAddress((void**)&Xg_w,   g_Xg_w);
    cudaGetSymbolAddress((void**)&Xc_w,   g_Xc_w);
    cudaGetSymbolAddress((void**)&Hw,     g_Hw);
    cudaGetSymbolAddress((void**)&Uw,     g_Uw);
    cudaGetSymbolAddress((void**)&Pg,     g_Pg);
    cudaGetSymbolAddress((void**)&Pc,     g_Pc);
    cudaGetSymbolAddress((void**)&states, g_states);
    cudaGetSymbolAddress((void**)&hidden, g_hidden);
    cudaGetSymbolAddress((void**)&bar,    g_bar);
    cudaGetSymbolAddress((void**)&ceh, g_ceh);
    cudaGetSymbolAddress((void**)&cel, g_cel);
    cudaGetSymbolAddress((void**)&uAh, g_uAh);
    cudaGetSymbolAddress((void**)&uAl, g_uAl);
    cudaGetSymbolAddress((void**)&weAh, g_weAh);
    cudaGetSymbolAddress((void**)&weAl, g_weAl);
    cudaGetSymbolAddress((void**)&Hch, g_Hch);
    cudaGetSymbolAddress((void**)&Hcl, g_Hcl);
    cudaGetSymbolAddress((void**)&RHh, g_RHh);
    cudaGetSymbolAddress((void**)&RHl, g_RHl);
    cudaGetSymbolAddress((void**)&Hwh, g_Hwh);
    cudaGetSymbolAddress((void**)&Hwl, g_Hwl);
    cudaGetSymbolAddress((void**)&RHwh, g_RHwh);
    cudaGetSymbolAddress((void**)&RHwl, g_RHwl);
    cudaGetSymbolAddress((void**)&Wgc_h, g_Wgc_h);
    cudaGetSymbolAddress((void**)&Wgc_l, g_Wgc_l);
    cudaGetSymbolAddress((void**)&Wcc_h, g_Wcc_h);
    cudaGetSymbolAddress((void**)&Wcc_l, g_Wcc_l);
    cudaGetSymbolAddress((void**)&Wgwcs_h, g_Wgwcs_h);
    cudaGetSymbolAddress((void**)&Wgwcs_l, g_Wgwcs_l);
    cudaGetSymbolAddress((void**)&Wcwcs_h, g_Wcwcs_h);
    cudaGetSymbolAddress((void**)&Wcwcs_l, g_Wcwcs_l);
    cudaGetSymbolAddress((void**)&Wgwwe_h, g_Wgwwe_h);
    cudaGetSymbolAddress((void**)&Wgwwe_l, g_Wgwwe_l);
    cudaGetSymbolAddress((void**)&Wcwwe_h, g_Wcwwe_h);
    cudaGetSymbolAddress((void**)&Wcwwe_l, g_Wcwwe_l);
    cudaGetSymbolAddress((void**)&Wghc_h, g_Wghc_h);
    cudaGetSymbolAddress((void**)&Wghc_l, g_Wghc_l);
    cudaGetSymbolAddress((void**)&Wchc_h, g_Wchc_h);
    cudaGetSymbolAddress((void**)&Wchc_l, g_Wchc_l);
    cudaGetSymbolAddress((void**)&Wghw_h, g_Wghw_h);
    cudaGetSymbolAddress((void**)&Wghw_l, g_Wghw_l);
    cudaGetSymbolAddress((void**)&Wchw_h, g_Wchw_h);
    cudaGetSymbolAddress((void**)&Wchw_l, g_Wchw_l);

    // ---- one fused weight-split launch ----
    k_prep_all<<<(Q10 + 255) / 256, 256>>>(Wg_c, Wc_c, Wg_w, Wc_w,
        Wgc_h, Wgc_l, Wcc_h, Wcc_l,
        Wgwcs_h, Wgwcs_l, Wcwcs_h, Wcwcs_l,
        Wgwwe_h, Wgwwe_l, Wcwwe_h, Wcwwe_l,
        Wghc_h, Wghc_l, Wchc_h, Wchc_l, Wghw_h, Wghw_l, Wchw_h, Wchw_l);
    cudaMemsetAsync(bar, 0, (2 * TC * 32 + 2 * TW * 8) * sizeof(int));

    // ---- per-character x-proj tables: Eg = char_emb@Wxg + bg, Ec likewise ----
    k_split_ce<<<(NC * CE + 255) / 256, 256>>>(char_emb, ceh, cel);
    k_mm_bias_t<false><<<dim3(8, NC / 128), 256>>>(ceh, cel, Wgc_h, Wgc_l, bg_c, Eg, 1024, CE / 32);
    k_mm_bias_t<false><<<dim3(4, NC / 128), 256>>>(ceh, cel, Wcc_h, Wcc_l, bc_c, Ec, 512, CE / 32);
    cudaMemsetAsync(Hc, 0, (size_t)2 * U_ * H * sizeof(float));
    cudaMemsetAsync(Hch, 0, (size_t)2 * U_ * H * sizeof(__nv_bfloat16));
    cudaMemsetAsync(Hcl, 0, (size_t)2 * U_ * H * sizeof(__nv_bfloat16));

    // char recurrence: ONE persistent kernel, per-mtile group barriers,
    // x-projections read from L2-resident per-character tables
    k_char_rnn<<<128, 256>>>(Wghc_h, Wghc_l, Wchc_h, Wchc_l,
                             Eg, Ec, charseqs, charseq_lens,
                             Hc, Uc, Hch, Hcl, RHh, RHl, bar);

    // ---- word x-projections via unique-word factorization ----
    k_build_u<<<(U_ * 2 * H + 255) / 256, 256>>>(Hc, uAh, uAl);
    k_mm_bias_t<false><<<dim3(8, U_ / 128), 256>>>(uAh, uAl, Wgwcs_h, Wgwcs_l, bg_w, Pg, 1024, (2 * H) / 32);
    k_mm_bias_t<false><<<dim3(4, U_ / 128), 256>>>(uAh, uAl, Wcwcs_h, Wcwcs_l, bc_w, Pc, 512, (2 * H) / 32);
    k_combine<<<(B_ * TW * 384 + 255) / 256, 256>>>(charseq_ids, Pg, Pc, Xg_w, Xc_w);
    k_gather_we<<<(B_ * TW * WE + 255) / 256, 256>>>(word_ids, word_emb, weAh, weAl);
    k_mm_bias_t<true><<<dim3(8, (B_ * TW) / 128), 256>>>(weAh, weAl, Wgwwe_h, Wgwwe_l, bg_w, Xg_w, 1024, WE / 32);
    k_mm_bias_t<true><<<dim3(4, (B_ * TW) / 128), 256>>>(weAh, weAl, Wcwwe_h, Wcwwe_l, bc_w, Xc_w, 512, WE / 32);

    cudaMemsetAsync(Hw, 0, (size_t)2 * B_ * H * sizeof(float));
    cudaMemsetAsync(Hwh, 0, (size_t)2 * B_ * H * sizeof(__nv_bfloat16));
    cudaMemsetAsync(Hwl, 0, (size_t)2 * B_ * H * sizeof(__nv_bfloat16));

    // word recurrence: ONE persistent kernel, per-mtile group barriers
    k_word_rnn<<<128, 128>>>(Wghw_h, Wghw_l, Wchw_h, Wchw_l,
                             Xg_w, Xc_w, sentence_lens,
                             Hw, Uw, Hwh, Hwl, RHwh, RHwl, bar + 2 * TC * 32);

    // ---- head ----
    k_copy_states<<<(B_ * 2 * H + 255) / 256, 256>>>(Hw, states);
    k_sgemm_bias_s<<<dim3(1, B_ / 64), 256>>>(states, W1, b1, hidden, 64, 2 * H, 1);
    k_fc2<<<(B_ * 2 + 255) / 256, 256>>>(hidden, W2, b2, out);
}